// round 3
// baseline (speedup 1.0000x reference)
#include <cuda_runtime.h>
#include <cstdint>

#define NNODES 50000
#define NEDGES 800000
#define C_IN   512
#define C_HID  128
#define HEADS2 3
#define C_OUT  2
#define TOTE   (NEDGES + NNODES)   // edges + self loops
#define AGG_CAP 2048
#define NEG_SLOPE 0.2f

// ---------------- scratch (static __device__, no allocations) ----------------
__device__ float g_h1[(size_t)NNODES * C_HID];     // x @ W1
__device__ float g_out1[(size_t)NNODES * C_HID];   // relu(agg1 + b1)
__device__ float g_asrc1[NNODES];
__device__ float g_adst1[NNODES];
__device__ float g_h2[(size_t)NNODES * 6];         // layer2 features [N,3,2]
__device__ float g_asrc2[(size_t)NNODES * 3];
__device__ float g_adst2[(size_t)NNODES * 3];
__device__ int   g_deg[NNODES];
__device__ int   g_off[NNODES];
__device__ int   g_pos[NNODES];
__device__ int   g_esrc[TOTE];                     // src node per edge, grouped by dst
__device__ int   g_is64;                           // edge_index dtype flag

// ---------------- dtype detection for edge_index ----------------
__global__ void detect_kernel(const unsigned* __restrict__ ei_words) {
    // If int64 with non-negative values < 2^31, every odd 32-bit word is 0.
    // If int32, odd words are random node ids (P(all 64 zero) ~ 0).
    int flag = 1;
    for (int i = 0; i < 64; i++)
        if (ei_words[2 * i + 1] != 0u) { flag = 0; break; }
    g_is64 = flag;
}

__device__ __forceinline__ void load_edge(const void* ei, int e, int& s, int& d) {
    if (g_is64) {
        const long long* p = (const long long*)ei;
        s = (int)p[e];
        d = (int)p[NEDGES + e];
    } else {
        const int* p = (const int*)ei;
        s = p[e];
        d = p[NEDGES + e];
    }
}

// ---------------- CSR build ----------------
__global__ void init_deg_kernel() {
    int i = blockIdx.x * blockDim.x + threadIdx.x;
    if (i < NNODES) g_deg[i] = 1;   // self loop
}

__global__ void count_kernel(const void* __restrict__ ei) {
    int e = blockIdx.x * blockDim.x + threadIdx.x;
    if (e >= NEDGES) return;
    int s, d;
    load_edge(ei, e, s, d);
    atomicAdd(&g_deg[d], 1);
}

__global__ void scan_kernel() {
    const int T = 1024;
    const int per = (NNODES + T - 1) / T;   // 49
    __shared__ int ssum[T];
    int t = threadIdx.x;
    int base = t * per;
    int s = 0;
    for (int i = 0; i < per; i++) {
        int idx = base + i;
        if (idx < NNODES) s += g_deg[idx];
    }
    ssum[t] = s;
    __syncthreads();
    for (int off = 1; off < T; off <<= 1) {
        int v = (t >= off) ? ssum[t - off] : 0;
        __syncthreads();
        ssum[t] += v;
        __syncthreads();
    }
    int run = (t == 0) ? 0 : ssum[t - 1];
    for (int i = 0; i < per; i++) {
        int idx = base + i;
        if (idx < NNODES) {
            g_off[idx] = run;
            g_pos[idx] = run;
            run += g_deg[idx];
        }
    }
}

__global__ void scatter_kernel(const void* __restrict__ ei) {
    int idx = blockIdx.x * blockDim.x + threadIdx.x;
    if (idx < NEDGES) {
        int s, d;
        load_edge(ei, idx, s, d);
        int p = atomicAdd(&g_pos[d], 1);
        g_esrc[p] = s;
    } else if (idx < TOTE) {
        int i = idx - NEDGES;           // self loop
        int p = atomicAdd(&g_pos[i], 1);
        g_esrc[p] = i;
    }
}

// ---------------- SGEMM: g_h1 = x @ W1  (M x 512 @ 512 x 128) ----------------
__global__ __launch_bounds__(256) void sgemm1_kernel(
    const float* __restrict__ A,   // [M, 512]
    const float* __restrict__ B)   // [512, 128]
{
    const int K = C_IN;
    __shared__ float As[8][128];   // transposed: As[k][m]
    __shared__ float Bs[8][128];   // Bs[k][n]

    int tid = threadIdx.x;
    int m0 = blockIdx.x * 128;

    int arow = tid >> 1;
    int acol = (tid & 1) * 4;
    int brow = tid >> 5;
    int bcol = (tid & 31) * 4;
    int tx = tid & 15;
    int ty = tid >> 4;

    float acc[8][8];
#pragma unroll
    for (int i = 0; i < 8; i++)
#pragma unroll
        for (int j = 0; j < 8; j++) acc[i][j] = 0.f;

    for (int k0 = 0; k0 < K; k0 += 8) {
        float4 av = make_float4(0.f, 0.f, 0.f, 0.f);
        int gm = m0 + arow;
        if (gm < NNODES)
            av = *(const float4*)(A + (size_t)gm * K + k0 + acol);
        As[acol + 0][arow] = av.x;
        As[acol + 1][arow] = av.y;
        As[acol + 2][arow] = av.z;
        As[acol + 3][arow] = av.w;

        float4 bv = *(const float4*)(B + (size_t)(k0 + brow) * 128 + bcol);
        *(float4*)&Bs[brow][bcol] = bv;
        __syncthreads();

#pragma unroll
        for (int k = 0; k < 8; k++) {
            float4 a0 = *(float4*)&As[k][ty * 4];
            float4 a1 = *(float4*)&As[k][64 + ty * 4];
            float4 b0 = *(float4*)&Bs[k][tx * 4];
            float4 b1 = *(float4*)&Bs[k][64 + tx * 4];
            float a[8] = {a0.x, a0.y, a0.z, a0.w, a1.x, a1.y, a1.z, a1.w};
            float b[8] = {b0.x, b0.y, b0.z, b0.w, b1.x, b1.y, b1.z, b1.w};
#pragma unroll
            for (int i = 0; i < 8; i++)
#pragma unroll
                for (int j = 0; j < 8; j++) acc[i][j] += a[i] * b[j];
        }
        __syncthreads();
    }

#pragma unroll
    for (int ii = 0; ii < 2; ii++)
#pragma unroll
        for (int i = 0; i < 4; i++) {
            int row = m0 + ii * 64 + ty * 4 + i;
            if (row < NNODES) {
#pragma unroll
                for (int jj = 0; jj < 2; jj++) {
                    float4 v = make_float4(acc[ii * 4 + i][jj * 4 + 0],
                                           acc[ii * 4 + i][jj * 4 + 1],
                                           acc[ii * 4 + i][jj * 4 + 2],
                                           acc[ii * 4 + i][jj * 4 + 3]);
                    *(float4*)(g_h1 + (size_t)row * 128 + jj * 64 + tx * 4) = v;
                }
            }
        }
}

// ---------------- attention coefficients layer 1 ----------------
__global__ void att1_kernel(const float* __restrict__ att_src,
                            const float* __restrict__ att_dst) {
    int w = (blockIdx.x * blockDim.x + threadIdx.x) >> 5;
    if (w >= NNODES) return;
    int lane = threadIdx.x & 31;
    float4 hv = *(const float4*)(g_h1 + (size_t)w * 128 + lane * 4);
    float4 s4 = *(const float4*)(att_src + lane * 4);
    float4 d4 = *(const float4*)(att_dst + lane * 4);
    float ps = hv.x * s4.x + hv.y * s4.y + hv.z * s4.z + hv.w * s4.w;
    float pd = hv.x * d4.x + hv.y * d4.y + hv.z * d4.z + hv.w * d4.w;
#pragma unroll
    for (int o = 16; o > 0; o >>= 1) {
        ps += __shfl_xor_sync(0xffffffffu, ps, o);
        pd += __shfl_xor_sync(0xffffffffu, pd, o);
    }
    if (lane == 0) {
        g_asrc1[w] = ps;
        g_adst1[w] = pd;
    }
}

// ---------------- layer-1 softmax aggregation (block per dst node) ---------
__global__ __launch_bounds__(128) void agg1_kernel(const float* __restrict__ bias1) {
    int d = blockIdx.x;
    int t = threadIdx.x;
    int start = g_off[d];
    int cnt = g_deg[d];

    __shared__ float sh[AGG_CAP];
    __shared__ float red[128];

    float adst = g_adst1[d];

    // pass 1: e = leaky_relu(asrc[s] + adst), block max
    float mx = -3.4e38f;
    for (int j = t; j < cnt; j += 128) {
        int s = g_esrc[start + j];
        float e = g_asrc1[s] + adst;
        e = e >= 0.f ? e : NEG_SLOPE * e;
        if (j < AGG_CAP) sh[j] = e;
        mx = fmaxf(mx, e);
    }
    red[t] = mx;
    __syncthreads();
#pragma unroll
    for (int o = 64; o > 0; o >>= 1) {
        if (t < o) red[t] = fmaxf(red[t], red[t + o]);
        __syncthreads();
    }
    float m = red[0];
    __syncthreads();

    // pass 2: exp + block sum
    float sum = 0.f;
    for (int j = t; j < cnt; j += 128) {
        float e;
        if (j < AGG_CAP) e = sh[j];
        else {
            int s = g_esrc[start + j];
            e = g_asrc1[s] + adst;
            e = e >= 0.f ? e : NEG_SLOPE * e;
        }
        float ex = __expf(e - m);
        if (j < AGG_CAP) sh[j] = ex;
        sum += ex;
    }
    red[t] = sum;
    __syncthreads();
#pragma unroll
    for (int o = 64; o > 0; o >>= 1) {
        if (t < o) red[t] += red[t + o];
        __syncthreads();
    }
    float inv = 1.f / (red[0] + 1e-16f);

    // pass 3: channel-parallel weighted accumulation (thread t = channel t)
    float acc = 0.f;
    for (int j = 0; j < cnt; j++) {
        int s = g_esrc[start + j];
        float ex;
        if (j < AGG_CAP) ex = sh[j];
        else {
            float e = g_asrc1[s] + adst;
            e = e >= 0.f ? e : NEG_SLOPE * e;
            ex = __expf(e - m);
        }
        acc += g_h1[(size_t)s * 128 + t] * (ex * inv);
    }
    float v = acc + bias1[t];
    g_out1[(size_t)d * 128 + t] = v > 0.f ? v : 0.f;
}

// ---------------- layer 2 features + attention (warp per node) -------------
__global__ void layer2_kernel(const float* __restrict__ W2,     // [128,6]
                              const float* __restrict__ as2,    // [3,2]
                              const float* __restrict__ ad2) {  // [3,2]
    int w = (blockIdx.x * blockDim.x + threadIdx.x) >> 5;
    if (w >= NNODES) return;
    int lane = threadIdx.x & 31;
    float4 v = *(const float4*)(g_out1 + (size_t)w * 128 + lane * 4);
    float vals[4] = {v.x, v.y, v.z, v.w};
    float p[6] = {0.f, 0.f, 0.f, 0.f, 0.f, 0.f};
#pragma unroll
    for (int i = 0; i < 4; i++) {
        int c = lane * 4 + i;
        const float* wr = W2 + c * 6;
        float val = vals[i];
#pragma unroll
        for (int j = 0; j < 6; j++) p[j] += val * wr[j];
    }
#pragma unroll
    for (int o = 16; o > 0; o >>= 1)
#pragma unroll
        for (int j = 0; j < 6; j++) p[j] += __shfl_xor_sync(0xffffffffu, p[j], o);

    if (lane == 0) {
        float* hp = g_h2 + (size_t)w * 6;
#pragma unroll
        for (int j = 0; j < 6; j++) hp[j] = p[j];
        g_asrc2[w * 3 + 0] = p[0] * as2[0] + p[1] * as2[1];
        g_asrc2[w * 3 + 1] = p[2] * as2[2] + p[3] * as2[3];
        g_asrc2[w * 3 + 2] = p[4] * as2[4] + p[5] * as2[5];
        g_adst2[w * 3 + 0] = p[0] * ad2[0] + p[1] * ad2[1];
        g_adst2[w * 3 + 1] = p[2] * ad2[2] + p[3] * ad2[3];
        g_adst2[w * 3 + 2] = p[4] * ad2[4] + p[5] * ad2[5];
    }
}

// ---------------- layer-2 aggregation + head mean (warp per dst node) ------
__global__ void agg2_kernel(const float* __restrict__ bias2,
                            float* __restrict__ out) {
    int d = (blockIdx.x * blockDim.x + threadIdx.x) >> 5;
    if (d >= NNODES) return;
    int lane = threadIdx.x & 31;
    int start = g_off[d];
    int cnt = g_deg[d];

    float ad0 = g_adst2[d * 3 + 0];
    float ad1 = g_adst2[d * 3 + 1];
    float ad2v = g_adst2[d * 3 + 2];

    float m0 = -3.4e38f, m1 = -3.4e38f, m2 = -3.4e38f;
    for (int j = lane; j < cnt; j += 32) {
        int s = g_esrc[start + j];
        float e0 = g_asrc2[s * 3 + 0] + ad0; e0 = e0 >= 0.f ? e0 : NEG_SLOPE * e0;
        float e1 = g_asrc2[s * 3 + 1] + ad1; e1 = e1 >= 0.f ? e1 : NEG_SLOPE * e1;
        float e2 = g_asrc2[s * 3 + 2] + ad2v; e2 = e2 >= 0.f ? e2 : NEG_SLOPE * e2;
        m0 = fmaxf(m0, e0); m1 = fmaxf(m1, e1); m2 = fmaxf(m2, e2);
    }
#pragma unroll
    for (int o = 16; o > 0; o >>= 1) {
        m0 = fmaxf(m0, __shfl_xor_sync(0xffffffffu, m0, o));
        m1 = fmaxf(m1, __shfl_xor_sync(0xffffffffu, m1, o));
        m2 = fmaxf(m2, __shfl_xor_sync(0xffffffffu, m2, o));
    }

    float s0 = 0.f, s1 = 0.f, s2 = 0.f;
    for (int j = lane; j < cnt; j += 32) {
        int s = g_esrc[start + j];
        float e0 = g_asrc2[s * 3 + 0] + ad0; e0 = e0 >= 0.f ? e0 : NEG_SLOPE * e0;
        float e1 = g_asrc2[s * 3 + 1] + ad1; e1 = e1 >= 0.f ? e1 : NEG_SLOPE * e1;
        float e2 = g_asrc2[s * 3 + 2] + ad2v; e2 = e2 >= 0.f ? e2 : NEG_SLOPE * e2;
        s0 += __expf(e0 - m0); s1 += __expf(e1 - m1); s2 += __expf(e2 - m2);
    }
#pragma unroll
    for (int o = 16; o > 0; o >>= 1) {
        s0 += __shfl_xor_sync(0xffffffffu, s0, o);
        s1 += __shfl_xor_sync(0xffffffffu, s1, o);
        s2 += __shfl_xor_sync(0xffffffffu, s2, o);
    }
    float i0 = 1.f / (s0 + 1e-16f);
    float i1 = 1.f / (s1 + 1e-16f);
    float i2 = 1.f / (s2 + 1e-16f);

    float acc[6] = {0.f, 0.f, 0.f, 0.f, 0.f, 0.f};
    for (int j = lane; j < cnt; j += 32) {
        int s = g_esrc[start + j];
        float e0 = g_asrc2[s * 3 + 0] + ad0; e0 = e0 >= 0.f ? e0 : NEG_SLOPE * e0;
        float e1 = g_asrc2[s * 3 + 1] + ad1; e1 = e1 >= 0.f ? e1 : NEG_SLOPE * e1;
        float e2 = g_asrc2[s * 3 + 2] + ad2v; e2 = e2 >= 0.f ? e2 : NEG_SLOPE * e2;
        float a0 = __expf(e0 - m0) * i0;
        float a1 = __expf(e1 - m1) * i1;
        float a2 = __expf(e2 - m2) * i2;
        const float* hp = g_h2 + (size_t)s * 6;
        acc[0] += hp[0] * a0; acc[1] += hp[1] * a0;
        acc[2] += hp[2] * a1; acc[3] += hp[3] * a1;
        acc[4] += hp[4] * a2; acc[5] += hp[5] * a2;
    }
#pragma unroll
    for (int o = 16; o > 0; o >>= 1)
#pragma unroll
        for (int j = 0; j < 6; j++) acc[j] += __shfl_xor_sync(0xffffffffu, acc[j], o);

    if (lane == 0) {
        out[d * 2 + 0] = (acc[0] + acc[2] + acc[4]) * (1.f / 3.f) + bias2[0];
        out[d * 2 + 1] = (acc[1] + acc[3] + acc[5]) * (1.f / 3.f) + bias2[1];
    }
}

// ---------------- launch ----------------
extern "C" void kernel_launch(void* const* d_in, const int* in_sizes, int n_in,
                              void* d_out, int out_size) {
    const float* x   = (const float*)d_in[0];
    const void*  ei  = d_in[1];
    const float* W1  = (const float*)d_in[2];
    const float* as1 = (const float*)d_in[3];
    const float* ad1 = (const float*)d_in[4];
    const float* b1  = (const float*)d_in[5];
    const float* W2  = (const float*)d_in[6];
    const float* as2 = (const float*)d_in[7];
    const float* ad2 = (const float*)d_in[8];
    const float* b2  = (const float*)d_in[9];
    float* out = (float*)d_out;

    detect_kernel<<<1, 1>>>((const unsigned*)ei);

    // CSR build
    init_deg_kernel<<<(NNODES + 255) / 256, 256>>>();
    count_kernel<<<(NEDGES + 255) / 256, 256>>>(ei);
    scan_kernel<<<1, 1024>>>();
    scatter_kernel<<<(TOTE + 255) / 256, 256>>>(ei);

    // Layer 1
    sgemm1_kernel<<<(NNODES + 127) / 128, 256>>>(x, W1);
    att1_kernel<<<(NNODES + 7) / 8, 256>>>(as1, ad1);
    agg1_kernel<<<NNODES, 128>>>(b1);

    // Layer 2
    layer2_kernel<<<(NNODES + 7) / 8, 256>>>(W2, as2, ad2);
    agg2_kernel<<<(NNODES + 7) / 8, 256>>>(b2, out);
}

// round 6
// speedup vs baseline: 1.5740x; 1.5740x over previous
#include <cuda_runtime.h>
#include <cuda_bf16.h>
#include <cstdint>

#define NNODES 50000
#define NEDGES 800000
#define C_IN   512
#define C_HID  128
#define HEADS2 3
#define C_OUT  2
#define TOTE   (NEDGES + NNODES)   // edges + self loops
#define AGG_CAP 2048
#define NEG_SLOPE 0.2f
#define SCAN_B ((NNODES + 255) / 256)   // 196

// ---------------- scratch (static __device__, no allocations) ----------------
__device__ float g_h1[(size_t)NNODES * C_HID];     // x @ W1
__device__ float g_out1[(size_t)NNODES * C_HID];   // relu(agg1 + b1)
__device__ float g_asrc1[NNODES];
__device__ float g_adst1[NNODES];
__device__ float g_h2[(size_t)NNODES * 6];         // layer2 features [N,3,2]
__device__ float g_asrc2[(size_t)NNODES * 3];
__device__ float g_adst2[(size_t)NNODES * 3];
__device__ int   g_deg[NNODES];
__device__ int   g_off[NNODES];
__device__ int   g_pos[NNODES];
__device__ int   g_esrc[TOTE];                     // src node per edge, grouped by dst
__device__ int   g_is64;                           // edge_index dtype flag
__device__ int   g_bsum[SCAN_B];
__device__ int   g_bbase[SCAN_B];

// ---------------- dtype detection for edge_index ----------------
__global__ void detect_kernel(const unsigned* __restrict__ ei_words) {
    int flag = 1;
    for (int i = 0; i < 64; i++)
        if (ei_words[2 * i + 1] != 0u) { flag = 0; break; }
    g_is64 = flag;
}

__device__ __forceinline__ void load_edge(const void* ei, int e, int& s, int& d) {
    if (g_is64) {
        const long long* p = (const long long*)ei;
        s = (int)p[e];
        d = (int)p[NEDGES + e];
    } else {
        const int* p = (const int*)ei;
        s = p[e];
        d = p[NEDGES + e];
    }
}

// ---------------- CSR build ----------------
__global__ void init_deg_kernel() {
    int i = blockIdx.x * blockDim.x + threadIdx.x;
    if (i < NNODES) g_deg[i] = 1;   // self loop
}

__global__ void count_kernel(const void* __restrict__ ei) {
    int e = blockIdx.x * blockDim.x + threadIdx.x;
    if (e >= NEDGES) return;
    int s, d;
    load_edge(ei, e, s, d);
    atomicAdd(&g_deg[d], 1);
}

// ---- parallel 3-phase scan ----
__global__ void csr_partial_kernel() {
    int i = blockIdx.x * 256 + threadIdx.x;
    int v = (i < NNODES) ? g_deg[i] : 0;
#pragma unroll
    for (int o = 16; o > 0; o >>= 1) v += __shfl_xor_sync(0xffffffffu, v, o);
    __shared__ int ws[8];
    if ((threadIdx.x & 31) == 0) ws[threadIdx.x >> 5] = v;
    __syncthreads();
    if (threadIdx.x == 0) {
        int s = 0;
#pragma unroll
        for (int w = 0; w < 8; w++) s += ws[w];
        g_bsum[blockIdx.x] = s;
    }
}

__global__ void csr_scanbase_kernel() {
    int t = threadIdx.x;
    int lane = t & 31, w = t >> 5;
    int v = (t < SCAN_B) ? g_bsum[t] : 0;
    int incl = v;
#pragma unroll
    for (int o = 1; o < 32; o <<= 1) {
        int u = __shfl_up_sync(0xffffffffu, incl, o);
        if (lane >= o) incl += u;
    }
    __shared__ int ws[8], ws2[8];
    if (lane == 31) ws[w] = incl;
    __syncthreads();
    if (t < 8) {
        int wv = ws[t];
        int wi = wv;
#pragma unroll
        for (int o = 1; o < 8; o <<= 1) {
            int u = __shfl_up_sync(0xffu, wi, o);
            if (t >= o) wi += u;
        }
        ws2[t] = wi - wv;   // exclusive
    }
    __syncthreads();
    if (t < SCAN_B) g_bbase[t] = ws2[w] + incl - v;
}

__global__ void csr_offsets_kernel() {
    int b = blockIdx.x;
    int t = threadIdx.x;
    int i = b * 256 + t;
    int lane = t & 31, w = t >> 5;
    int v = (i < NNODES) ? g_deg[i] : 0;
    int incl = v;
#pragma unroll
    for (int o = 1; o < 32; o <<= 1) {
        int u = __shfl_up_sync(0xffffffffu, incl, o);
        if (lane >= o) incl += u;
    }
    __shared__ int ws[8], ws2[8];
    if (lane == 31) ws[w] = incl;
    __syncthreads();
    if (t < 8) {
        int wv = ws[t];
        int wi = wv;
#pragma unroll
        for (int o = 1; o < 8; o <<= 1) {
            int u = __shfl_up_sync(0xffu, wi, o);
            if (t >= o) wi += u;
        }
        ws2[t] = wi - wv;
    }
    __syncthreads();
    if (i < NNODES) {
        int off = g_bbase[b] + ws2[w] + incl - v;
        g_off[i] = off;
        g_pos[i] = off;
    }
}

__global__ void scatter_kernel(const void* __restrict__ ei) {
    int idx = blockIdx.x * blockDim.x + threadIdx.x;
    if (idx < NEDGES) {
        int s, d;
        load_edge(ei, idx, s, d);
        int p = atomicAdd(&g_pos[d], 1);
        g_esrc[p] = s;
    } else if (idx < TOTE) {
        int i = idx - NEDGES;           // self loop
        int p = atomicAdd(&g_pos[i], 1);
        g_esrc[p] = i;
    }
}

// ---------------- tensor-core GEMM: g_h1 = x @ W1 (bf16 3-term split) -------
// Block: 128(M) x 128(N), full K=512 loop, 256 threads = 8 warps (4x2 grid),
// warp tile 32x64, mma.sync.m16n8k16, f32 accumulate.
#define GK 32           // K chunk
#define AS 40           // A smem row stride (halves): 32 + 8 pad
#define BS 136          // B smem row stride (halves): 128 + 8 pad

__device__ __forceinline__ void mma16816(float* c, const uint32_t* a,
                                         uint32_t b0, uint32_t b1) {
    asm volatile(
        "mma.sync.aligned.m16n8k16.row.col.f32.bf16.bf16.f32 "
        "{%0,%1,%2,%3},{%4,%5,%6,%7},{%8,%9},{%0,%1,%2,%3};"
        : "+f"(c[0]), "+f"(c[1]), "+f"(c[2]), "+f"(c[3])
        : "r"(a[0]), "r"(a[1]), "r"(a[2]), "r"(a[3]), "r"(b0), "r"(b1));
}

__global__ __launch_bounds__(256) void gemm1_bf16_kernel(
    const float* __restrict__ A,   // x  [NNODES, 512]
    const float* __restrict__ B)   // W1 [512, 128]
{
    __shared__ __align__(16) __nv_bfloat16 Ah[128][AS];
    __shared__ __align__(16) __nv_bfloat16 Al[128][AS];
    __shared__ __align__(16) __nv_bfloat16 Bh[GK][BS];
    __shared__ __align__(16) __nv_bfloat16 Bl[GK][BS];

    const int tid = threadIdx.x;
    const int lane = tid & 31;
    const int wid = tid >> 5;
    const int warp_m = wid & 3;       // 0..3
    const int warp_n = wid >> 2;      // 0..1
    const int g = lane >> 2;          // group 0..7
    const int t4 = lane & 3;          // 0..3
    const int m0 = blockIdx.x * 128;

    float acc[2][8][4];
#pragma unroll
    for (int mi = 0; mi < 2; mi++)
#pragma unroll
        for (int ni = 0; ni < 8; ni++)
#pragma unroll
            for (int q = 0; q < 4; q++) acc[mi][ni][q] = 0.f;

    // prefetch registers
    float4 pa[4], pb[4];

    // A element map: flat = i*256+tid; row = flat>>3, col4 = (flat&7)*4
    // B element map: flat = i*256+tid; krow = flat>>5, ncol4 = (flat&31)*4
#pragma unroll
    for (int i = 0; i < 4; i++) {
        int flat = i * 256 + tid;
        int row = flat >> 3, c4 = (flat & 7) * 4;
        int gr = m0 + row;
        pa[i] = (gr < NNODES) ? *(const float4*)(A + (size_t)gr * C_IN + c4)
                              : make_float4(0.f, 0.f, 0.f, 0.f);
        int kr = flat >> 5, n4 = (flat & 31) * 4;
        pb[i] = *(const float4*)(B + (size_t)kr * C_HID + n4);
    }

    const unsigned short* bhp = (const unsigned short*)&Bh[0][0];
    const unsigned short* blp = (const unsigned short*)&Bl[0][0];

    for (int kc = 0; kc < C_IN / GK; kc++) {
        // convert + store prefetched chunk to smem
#pragma unroll
        for (int i = 0; i < 4; i++) {
            int flat = i * 256 + tid;
            int row = flat >> 3, c4 = (flat & 7) * 4;
            float4 v = pa[i];
            __nv_bfloat162 h01 = __floats2bfloat162_rn(v.x, v.y);
            __nv_bfloat162 h23 = __floats2bfloat162_rn(v.z, v.w);
            float r0 = v.x - __bfloat162float(h01.x);
            float r1 = v.y - __bfloat162float(h01.y);
            float r2 = v.z - __bfloat162float(h23.x);
            float r3 = v.w - __bfloat162float(h23.y);
            __nv_bfloat162 l01 = __floats2bfloat162_rn(r0, r1);
            __nv_bfloat162 l23 = __floats2bfloat162_rn(r2, r3);
            *(__nv_bfloat162*)&Ah[row][c4]     = h01;
            *(__nv_bfloat162*)&Ah[row][c4 + 2] = h23;
            *(__nv_bfloat162*)&Al[row][c4]     = l01;
            *(__nv_bfloat162*)&Al[row][c4 + 2] = l23;

            int kr = flat >> 5, n4 = (flat & 31) * 4;
            float4 w = pb[i];
            __nv_bfloat162 wh01 = __floats2bfloat162_rn(w.x, w.y);
            __nv_bfloat162 wh23 = __floats2bfloat162_rn(w.z, w.w);
            float s0 = w.x - __bfloat162float(wh01.x);
            float s1 = w.y - __bfloat162float(wh01.y);
            float s2 = w.z - __bfloat162float(wh23.x);
            float s3 = w.w - __bfloat162float(wh23.y);
            __nv_bfloat162 wl01 = __floats2bfloat162_rn(s0, s1);
            __nv_bfloat162 wl23 = __floats2bfloat162_rn(s2, s3);
            *(__nv_bfloat162*)&Bh[kr][n4]     = wh01;
            *(__nv_bfloat162*)&Bh[kr][n4 + 2] = wh23;
            *(__nv_bfloat162*)&Bl[kr][n4]     = wl01;
            *(__nv_bfloat162*)&Bl[kr][n4 + 2] = wl23;
        }
        __syncthreads();

        // prefetch next chunk
        if (kc + 1 < C_IN / GK) {
            int k0n = (kc + 1) * GK;
#pragma unroll
            for (int i = 0; i < 4; i++) {
                int flat = i * 256 + tid;
                int row = flat >> 3, c4 = (flat & 7) * 4;
                int gr = m0 + row;
                pa[i] = (gr < NNODES)
                          ? *(const float4*)(A + (size_t)gr * C_IN + k0n + c4)
                          : make_float4(0.f, 0.f, 0.f, 0.f);
                int kr = flat >> 5, n4 = (flat & 31) * 4;
                pb[i] = *(const float4*)(B + (size_t)(k0n + kr) * C_HID + n4);
            }
        }

        // compute: two k16 steps per chunk
#pragma unroll
        for (int s = 0; s < GK; s += 16) {
            uint32_t ah[2][4], al[2][4];
#pragma unroll
            for (int mi = 0; mi < 2; mi++) {
                int r = warp_m * 32 + mi * 16 + g;
                int c = s + t4 * 2;
                ah[mi][0] = *(const uint32_t*)&Ah[r][c];
                ah[mi][1] = *(const uint32_t*)&Ah[r + 8][c];
                ah[mi][2] = *(const uint32_t*)&Ah[r][c + 8];
                ah[mi][3] = *(const uint32_t*)&Ah[r + 8][c + 8];
                al[mi][0] = *(const uint32_t*)&Al[r][c];
                al[mi][1] = *(const uint32_t*)&Al[r + 8][c];
                al[mi][2] = *(const uint32_t*)&Al[r][c + 8];
                al[mi][3] = *(const uint32_t*)&Al[r + 8][c + 8];
            }
#pragma unroll
            for (int ni = 0; ni < 8; ni++) {
                int n = warp_n * 64 + ni * 8 + g;
                int k0 = s + t4 * 2;
                uint32_t bh0 = (uint32_t)bhp[k0 * BS + n] |
                               ((uint32_t)bhp[(k0 + 1) * BS + n] << 16);
                uint32_t bh1 = (uint32_t)bhp[(k0 + 8) * BS + n] |
                               ((uint32_t)bhp[(k0 + 9) * BS + n] << 16);
                uint32_t bl0 = (uint32_t)blp[k0 * BS + n] |
                               ((uint32_t)blp[(k0 + 1) * BS + n] << 16);
                uint32_t bl1 = (uint32_t)blp[(k0 + 8) * BS + n] |
                               ((uint32_t)blp[(k0 + 9) * BS + n] << 16);
#pragma unroll
                for (int mi = 0; mi < 2; mi++) {
                    mma16816(acc[mi][ni], ah[mi], bh0, bh1);   // hi*hi
                    mma16816(acc[mi][ni], ah[mi], bl0, bl1);   // hi*lo
                    mma16816(acc[mi][ni], al[mi], bh0, bh1);   // lo*hi
                }
            }
        }
        __syncthreads();
    }

    // epilogue
#pragma unroll
    for (int mi = 0; mi < 2; mi++) {
#pragma unroll
        for (int ni = 0; ni < 8; ni++) {
            int r = m0 + warp_m * 32 + mi * 16 + g;
            int c = warp_n * 64 + ni * 8 + t4 * 2;
            if (r < NNODES)
                *(float2*)(g_h1 + (size_t)r * C_HID + c) =
                    make_float2(acc[mi][ni][0], acc[mi][ni][1]);
            if (r + 8 < NNODES)
                *(float2*)(g_h1 + (size_t)(r + 8) * C_HID + c) =
                    make_float2(acc[mi][ni][2], acc[mi][ni][3]);
        }
    }
}

// ---------------- attention coefficients layer 1 ----------------
__global__ void att1_kernel(const float* __restrict__ att_src,
                            const float* __restrict__ att_dst) {
    int w = (blockIdx.x * blockDim.x + threadIdx.x) >> 5;
    if (w >= NNODES) return;
    int lane = threadIdx.x & 31;
    float4 hv = *(const float4*)(g_h1 + (size_t)w * 128 + lane * 4);
    float4 s4 = *(const float4*)(att_src + lane * 4);
    float4 d4 = *(const float4*)(att_dst + lane * 4);
    float ps = hv.x * s4.x + hv.y * s4.y + hv.z * s4.z + hv.w * s4.w;
    float pd = hv.x * d4.x + hv.y * d4.y + hv.z * d4.z + hv.w * d4.w;
#pragma unroll
    for (int o = 16; o > 0; o >>= 1) {
        ps += __shfl_xor_sync(0xffffffffu, ps, o);
        pd += __shfl_xor_sync(0xffffffffu, pd, o);
    }
    if (lane == 0) {
        g_asrc1[w] = ps;
        g_adst1[w] = pd;
    }
}

// ---------------- layer-1 softmax aggregation (block per dst node) ---------
__global__ __launch_bounds__(128) void agg1_kernel(const float* __restrict__ bias1) {
    int d = blockIdx.x;
    int t = threadIdx.x;
    int start = g_off[d];
    int cnt = g_deg[d];

    __shared__ float sh[AGG_CAP];
    __shared__ float red[128];

    float adst = g_adst1[d];

    float mx = -3.4e38f;
    for (int j = t; j < cnt; j += 128) {
        int s = g_esrc[start + j];
        float e = g_asrc1[s] + adst;
        e = e >= 0.f ? e : NEG_SLOPE * e;
        if (j < AGG_CAP) sh[j] = e;
        mx = fmaxf(mx, e);
    }
    red[t] = mx;
    __syncthreads();
#pragma unroll
    for (int o = 64; o > 0; o >>= 1) {
        if (t < o) red[t] = fmaxf(red[t], red[t + o]);
        __syncthreads();
    }
    float m = red[0];
    __syncthreads();

    float sum = 0.f;
    for (int j = t; j < cnt; j += 128) {
        float e;
        if (j < AGG_CAP) e = sh[j];
        else {
            int s = g_esrc[start + j];
            e = g_asrc1[s] + adst;
            e = e >= 0.f ? e : NEG_SLOPE * e;
        }
        float ex = __expf(e - m);
        if (j < AGG_CAP) sh[j] = ex;
        sum += ex;
    }
    red[t] = sum;
    __syncthreads();
#pragma unroll
    for (int o = 64; o > 0; o >>= 1) {
        if (t < o) red[t] += red[t + o];
        __syncthreads();
    }
    float inv = 1.f / (red[0] + 1e-16f);

    float acc = 0.f;
    for (int j = 0; j < cnt; j++) {
        int s = g_esrc[start + j];
        float ex;
        if (j < AGG_CAP) ex = sh[j];
        else {
            float e = g_asrc1[s] + adst;
            e = e >= 0.f ? e : NEG_SLOPE * e;
            ex = __expf(e - m);
        }
        acc += g_h1[(size_t)s * 128 + t] * (ex * inv);
    }
    float v = acc + bias1[t];
    g_out1[(size_t)d * 128 + t] = v > 0.f ? v : 0.f;
}

// ---------------- layer 2 features + attention (warp per node) -------------
__global__ void layer2_kernel(const float* __restrict__ W2,     // [128,6]
                              const float* __restrict__ as2,    // [3,2]
                              const float* __restrict__ ad2) {  // [3,2]
    int w = (blockIdx.x * blockDim.x + threadIdx.x) >> 5;
    if (w >= NNODES) return;
    int lane = threadIdx.x & 31;
    float4 v = *(const float4*)(g_out1 + (size_t)w * 128 + lane * 4);
    float vals[4] = {v.x, v.y, v.z, v.w};
    float p[6] = {0.f, 0.f, 0.f, 0.f, 0.f, 0.f};
#pragma unroll
    for (int i = 0; i < 4; i++) {
        int c = lane * 4 + i;
        const float* wr = W2 + c * 6;
        float val = vals[i];
#pragma unroll
        for (int j = 0; j < 6; j++) p[j] += val * wr[j];
    }
#pragma unroll
    for (int o = 16; o > 0; o >>= 1)
#pragma unroll
        for (int j = 0; j < 6; j++) p[j] += __shfl_xor_sync(0xffffffffu, p[j], o);

    if (lane == 0) {
        float* hp = g_h2 + (size_t)w * 6;
#pragma unroll
        for (int j = 0; j < 6; j++) hp[j] = p[j];
        g_asrc2[w * 3 + 0] = p[0] * as2[0] + p[1] * as2[1];
        g_asrc2[w * 3 + 1] = p[2] * as2[2] + p[3] * as2[3];
        g_asrc2[w * 3 + 2] = p[4] * as2[4] + p[5] * as2[5];
        g_adst2[w * 3 + 0] = p[0] * ad2[0] + p[1] * ad2[1];
        g_adst2[w * 3 + 1] = p[2] * ad2[2] + p[3] * ad2[3];
        g_adst2[w * 3 + 2] = p[4] * ad2[4] + p[5] * ad2[5];
    }
}

// ---------------- layer-2 aggregation + head mean (warp per dst node) ------
__global__ void agg2_kernel(const float* __restrict__ bias2,
                            float* __restrict__ out) {
    int d = (blockIdx.x * blockDim.x + threadIdx.x) >> 5;
    if (d >= NNODES) return;
    int lane = threadIdx.x & 31;
    int start = g_off[d];
    int cnt = g_deg[d];

    float ad0 = g_adst2[d * 3 + 0];
    float ad1 = g_adst2[d * 3 + 1];
    float ad2v = g_adst2[d * 3 + 2];

    float m0 = -3.4e38f, m1 = -3.4e38f, m2 = -3.4e38f;
    for (int j = lane; j < cnt; j += 32) {
        int s = g_esrc[start + j];
        float e0 = g_asrc2[s * 3 + 0] + ad0; e0 = e0 >= 0.f ? e0 : NEG_SLOPE * e0;
        float e1 = g_asrc2[s * 3 + 1] + ad1; e1 = e1 >= 0.f ? e1 : NEG_SLOPE * e1;
        float e2 = g_asrc2[s * 3 + 2] + ad2v; e2 = e2 >= 0.f ? e2 : NEG_SLOPE * e2;
        m0 = fmaxf(m0, e0); m1 = fmaxf(m1, e1); m2 = fmaxf(m2, e2);
    }
#pragma unroll
    for (int o = 16; o > 0; o >>= 1) {
        m0 = fmaxf(m0, __shfl_xor_sync(0xffffffffu, m0, o));
        m1 = fmaxf(m1, __shfl_xor_sync(0xffffffffu, m1, o));
        m2 = fmaxf(m2, __shfl_xor_sync(0xffffffffu, m2, o));
    }

    float s0 = 0.f, s1 = 0.f, s2 = 0.f;
    for (int j = lane; j < cnt; j += 32) {
        int s = g_esrc[start + j];
        float e0 = g_asrc2[s * 3 + 0] + ad0; e0 = e0 >= 0.f ? e0 : NEG_SLOPE * e0;
        float e1 = g_asrc2[s * 3 + 1] + ad1; e1 = e1 >= 0.f ? e1 : NEG_SLOPE * e1;
        float e2 = g_asrc2[s * 3 + 2] + ad2v; e2 = e2 >= 0.f ? e2 : NEG_SLOPE * e2;
        s0 += __expf(e0 - m0); s1 += __expf(e1 - m1); s2 += __expf(e2 - m2);
    }
#pragma unroll
    for (int o = 16; o > 0; o >>= 1) {
        s0 += __shfl_xor_sync(0xffffffffu, s0, o);
        s1 += __shfl_xor_sync(0xffffffffu, s1, o);
        s2 += __shfl_xor_sync(0xffffffffu, s2, o);
    }
    float i0 = 1.f / (s0 + 1e-16f);
    float i1 = 1.f / (s1 + 1e-16f);
    float i2 = 1.f / (s2 + 1e-16f);

    float acc[6] = {0.f, 0.f, 0.f, 0.f, 0.f, 0.f};
    for (int j = lane; j < cnt; j += 32) {
        int s = g_esrc[start + j];
        float e0 = g_asrc2[s * 3 + 0] + ad0; e0 = e0 >= 0.f ? e0 : NEG_SLOPE * e0;
        float e1 = g_asrc2[s * 3 + 1] + ad1; e1 = e1 >= 0.f ? e1 : NEG_SLOPE * e1;
        float e2 = g_asrc2[s * 3 + 2] + ad2v; e2 = e2 >= 0.f ? e2 : NEG_SLOPE * e2;
        float a0 = __expf(e0 - m0) * i0;
        float a1 = __expf(e1 - m1) * i1;
        float a2 = __expf(e2 - m2) * i2;
        const float* hp = g_h2 + (size_t)s * 6;
        acc[0] += hp[0] * a0; acc[1] += hp[1] * a0;
        acc[2] += hp[2] * a1; acc[3] += hp[3] * a1;
        acc[4] += hp[4] * a2; acc[5] += hp[5] * a2;
    }
#pragma unroll
    for (int o = 16; o > 0; o >>= 1)
#pragma unroll
        for (int j = 0; j < 6; j++) acc[j] += __shfl_xor_sync(0xffffffffu, acc[j], o);

    if (lane == 0) {
        out[d * 2 + 0] = (acc[0] + acc[2] + acc[4]) * (1.f / 3.f) + bias2[0];
        out[d * 2 + 1] = (acc[1] + acc[3] + acc[5]) * (1.f / 3.f) + bias2[1];
    }
}

// ---------------- launch ----------------
extern "C" void kernel_launch(void* const* d_in, const int* in_sizes, int n_in,
                              void* d_out, int out_size) {
    const float* x   = (const float*)d_in[0];
    const void*  ei  = d_in[1];
    const float* W1  = (const float*)d_in[2];
    const float* as1 = (const float*)d_in[3];
    const float* ad1 = (const float*)d_in[4];
    const float* b1  = (const float*)d_in[5];
    const float* W2  = (const float*)d_in[6];
    const float* as2 = (const float*)d_in[7];
    const float* ad2 = (const float*)d_in[8];
    const float* b2  = (const float*)d_in[9];
    float* out = (float*)d_out;

    detect_kernel<<<1, 1>>>((const unsigned*)ei);

    // CSR build
    init_deg_kernel<<<(NNODES + 255) / 256, 256>>>();
    count_kernel<<<(NEDGES + 255) / 256, 256>>>(ei);
    csr_partial_kernel<<<SCAN_B, 256>>>();
    csr_scanbase_kernel<<<1, 256>>>();
    csr_offsets_kernel<<<SCAN_B, 256>>>();
    scatter_kernel<<<(TOTE + 255) / 256, 256>>>(ei);

    // Layer 1
    gemm1_bf16_kernel<<<(NNODES + 127) / 128, 256>>>(x, W1);
    att1_kernel<<<(NNODES + 7) / 8, 256>>>(as1, ad1);
    agg1_kernel<<<NNODES, 128>>>(b1);

    // Layer 2
    layer2_kernel<<<(NNODES + 7) / 8, 256>>>(W2, as2, ad2);
    agg2_kernel<<<(NNODES + 7) / 8, 256>>>(b2, out);
}

// round 7
// speedup vs baseline: 1.6673x; 1.0593x over previous
#include <cuda_runtime.h>
#include <cuda_bf16.h>
#include <cstdint>

#define NNODES 50000
#define NEDGES 800000
#define C_IN   512
#define C_HID  128
#define HEADS2 3
#define C_OUT  2
#define TOTE   (NEDGES + NNODES)   // edges + self loops
#define AGG_CAP 2048
#define NEG_SLOPE 0.2f
#define SCAN_B ((NNODES + 255) / 256)   // 196

// ---------------- scratch (static __device__, no allocations) ----------------
__device__ float g_h1[(size_t)NNODES * C_HID];     // x @ W1
__device__ float g_out1[(size_t)NNODES * C_HID];   // relu(agg1 + b1)
__device__ float g_asrc1[NNODES];
__device__ float g_adst1[NNODES];
__device__ float g_h2[(size_t)NNODES * 6];         // layer2 features [N,3,2]
__device__ float g_asrc2[(size_t)NNODES * 3];
__device__ float g_adst2[(size_t)NNODES * 3];
__device__ int   g_deg[NNODES];
__device__ int   g_off[NNODES];
__device__ int   g_pos[NNODES];
__device__ int   g_esrc[TOTE];                     // src node per edge, grouped by dst
__device__ int   g_is64;                           // edge_index dtype flag
__device__ int   g_bsum[SCAN_B];
__device__ int   g_bbase[SCAN_B];
// W1 pre-split into bf16 hi/lo planes, col-major [n][k] (n=0..127, k=0..511)
__device__ __align__(16) __nv_bfloat16 g_Bth[(size_t)C_HID * C_IN];
__device__ __align__(16) __nv_bfloat16 g_Btl[(size_t)C_HID * C_IN];

// ---------------- dtype detection for edge_index ----------------
__global__ void detect_kernel(const unsigned* __restrict__ ei_words) {
    int flag = 1;
    for (int i = 0; i < 64; i++)
        if (ei_words[2 * i + 1] != 0u) { flag = 0; break; }
    g_is64 = flag;
}

__device__ __forceinline__ void load_edge(const void* ei, int e, int& s, int& d) {
    if (g_is64) {
        const long long* p = (const long long*)ei;
        s = (int)p[e];
        d = (int)p[NEDGES + e];
    } else {
        const int* p = (const int*)ei;
        s = p[e];
        d = p[NEDGES + e];
    }
}

// ---------------- CSR build ----------------
__global__ void init_deg_kernel() {
    int i = blockIdx.x * blockDim.x + threadIdx.x;
    if (i < NNODES) g_deg[i] = 1;   // self loop
}

__global__ void count_kernel(const void* __restrict__ ei) {
    int e = blockIdx.x * blockDim.x + threadIdx.x;
    if (e >= NEDGES) return;
    int s, d;
    load_edge(ei, e, s, d);
    atomicAdd(&g_deg[d], 1);
}

// ---- parallel 3-phase scan ----
__global__ void csr_partial_kernel() {
    int i = blockIdx.x * 256 + threadIdx.x;
    int v = (i < NNODES) ? g_deg[i] : 0;
#pragma unroll
    for (int o = 16; o > 0; o >>= 1) v += __shfl_xor_sync(0xffffffffu, v, o);
    __shared__ int ws[8];
    if ((threadIdx.x & 31) == 0) ws[threadIdx.x >> 5] = v;
    __syncthreads();
    if (threadIdx.x == 0) {
        int s = 0;
#pragma unroll
        for (int w = 0; w < 8; w++) s += ws[w];
        g_bsum[blockIdx.x] = s;
    }
}

__global__ void csr_scanbase_kernel() {
    int t = threadIdx.x;
    int lane = t & 31, w = t >> 5;
    int v = (t < SCAN_B) ? g_bsum[t] : 0;
    int incl = v;
#pragma unroll
    for (int o = 1; o < 32; o <<= 1) {
        int u = __shfl_up_sync(0xffffffffu, incl, o);
        if (lane >= o) incl += u;
    }
    __shared__ int ws[8], ws2[8];
    if (lane == 31) ws[w] = incl;
    __syncthreads();
    if (t < 8) {
        int wv = ws[t];
        int wi = wv;
#pragma unroll
        for (int o = 1; o < 8; o <<= 1) {
            int u = __shfl_up_sync(0xffu, wi, o);
            if (t >= o) wi += u;
        }
        ws2[t] = wi - wv;   // exclusive
    }
    __syncthreads();
    if (t < SCAN_B) g_bbase[t] = ws2[w] + incl - v;
}

__global__ void csr_offsets_kernel() {
    int b = blockIdx.x;
    int t = threadIdx.x;
    int i = b * 256 + t;
    int lane = t & 31, w = t >> 5;
    int v = (i < NNODES) ? g_deg[i] : 0;
    int incl = v;
#pragma unroll
    for (int o = 1; o < 32; o <<= 1) {
        int u = __shfl_up_sync(0xffffffffu, incl, o);
        if (lane >= o) incl += u;
    }
    __shared__ int ws[8], ws2[8];
    if (lane == 31) ws[w] = incl;
    __syncthreads();
    if (t < 8) {
        int wv = ws[t];
        int wi = wv;
#pragma unroll
        for (int o = 1; o < 8; o <<= 1) {
            int u = __shfl_up_sync(0xffu, wi, o);
            if (t >= o) wi += u;
        }
        ws2[t] = wi - wv;
    }
    __syncthreads();
    if (i < NNODES) {
        int off = g_bbase[b] + ws2[w] + incl - v;
        g_off[i] = off;
        g_pos[i] = off;
    }
}

__global__ void scatter_kernel(const void* __restrict__ ei) {
    int idx = blockIdx.x * blockDim.x + threadIdx.x;
    if (idx < NEDGES) {
        int s, d;
        load_edge(ei, idx, s, d);
        int p = atomicAdd(&g_pos[d], 1);
        g_esrc[p] = s;
    } else if (idx < TOTE) {
        int i = idx - NEDGES;           // self loop
        int p = atomicAdd(&g_pos[i], 1);
        g_esrc[p] = i;
    }
}

// ---------------- W1 pre-split to bf16 hi/lo, col-major ----------------
__global__ void convertB_kernel(const float* __restrict__ W1) {
    int o = blockIdx.x * 256 + threadIdx.x;     // o = n*512 + k
    if (o >= C_HID * C_IN) return;
    int n = o >> 9, k = o & 511;
    float v = W1[(size_t)k * C_HID + n];
    __nv_bfloat16 h = __float2bfloat16(v);
    g_Bth[o] = h;
    g_Btl[o] = __float2bfloat16(v - __bfloat162float(h));
}

// ---------------- tensor-core GEMM: g_h1 = x @ W1 (bf16 3-term split) -------
// Block 128x128, 256 threads = 8 warps (4x2), warp tile 32x64, mma m16n8k16.
#define GK 32           // K chunk
#define AS 40           // A smem row stride (halves)
#define BTS 40          // Bt smem row stride (halves) — 20 words, conflict-free

__device__ __forceinline__ void mma16816(float* c, const uint32_t* a,
                                         uint32_t b0, uint32_t b1) {
    asm volatile(
        "mma.sync.aligned.m16n8k16.row.col.f32.bf16.bf16.f32 "
        "{%0,%1,%2,%3},{%4,%5,%6,%7},{%8,%9},{%0,%1,%2,%3};"
        : "+f"(c[0]), "+f"(c[1]), "+f"(c[2]), "+f"(c[3])
        : "r"(a[0]), "r"(a[1]), "r"(a[2]), "r"(a[3]), "r"(b0), "r"(b1));
}

__global__ __launch_bounds__(256) void gemm1_bf16_kernel(
    const float* __restrict__ A)   // x  [NNODES, 512]
{
    __shared__ __align__(16) __nv_bfloat16 Ah[128][AS];
    __shared__ __align__(16) __nv_bfloat16 Al[128][AS];
    __shared__ __align__(16) __nv_bfloat16 Bth_s[128][BTS];
    __shared__ __align__(16) __nv_bfloat16 Btl_s[128][BTS];

    const int tid = threadIdx.x;
    const int lane = tid & 31;
    const int wid = tid >> 5;
    const int warp_m = wid & 3;       // 0..3
    const int warp_n = wid >> 2;      // 0..1
    const int g = lane >> 2;          // 0..7
    const int t4 = lane & 3;          // 0..3
    const int m0 = blockIdx.x * 128;

    float acc[2][8][4];
#pragma unroll
    for (int mi = 0; mi < 2; mi++)
#pragma unroll
        for (int ni = 0; ni < 8; ni++)
#pragma unroll
            for (int q = 0; q < 4; q++) acc[mi][ni][q] = 0.f;

    float4 pa[4];
    uint4 pbh[2], pbl[2];

    // A map: flat = i*256+tid; row = flat>>3, col4 = (flat&7)*4
    // Bt map: u = i*256+tid; n = u>>2, kq = u&3 (16B quarters of 32-half row)
#pragma unroll
    for (int i = 0; i < 4; i++) {
        int flat = i * 256 + tid;
        int row = flat >> 3, c4 = (flat & 7) * 4;
        int gr = m0 + row;
        pa[i] = (gr < NNODES) ? *(const float4*)(A + (size_t)gr * C_IN + c4)
                              : make_float4(0.f, 0.f, 0.f, 0.f);
    }
#pragma unroll
    for (int i = 0; i < 2; i++) {
        int u = i * 256 + tid;
        int n = u >> 2, kq = u & 3;
        pbh[i] = *(const uint4*)(g_Bth + (size_t)n * C_IN + kq * 8);
        pbl[i] = *(const uint4*)(g_Btl + (size_t)n * C_IN + kq * 8);
    }

    for (int kc = 0; kc < C_IN / GK; kc++) {
        // stage prefetched chunk to smem
#pragma unroll
        for (int i = 0; i < 4; i++) {
            int flat = i * 256 + tid;
            int row = flat >> 3, c4 = (flat & 7) * 4;
            float4 v = pa[i];
            __nv_bfloat162 h01 = __floats2bfloat162_rn(v.x, v.y);
            __nv_bfloat162 h23 = __floats2bfloat162_rn(v.z, v.w);
            float r0 = v.x - __bfloat162float(h01.x);
            float r1 = v.y - __bfloat162float(h01.y);
            float r2 = v.z - __bfloat162float(h23.x);
            float r3 = v.w - __bfloat162float(h23.y);
            *(__nv_bfloat162*)&Ah[row][c4]     = h01;
            *(__nv_bfloat162*)&Ah[row][c4 + 2] = h23;
            *(__nv_bfloat162*)&Al[row][c4]     = __floats2bfloat162_rn(r0, r1);
            *(__nv_bfloat162*)&Al[row][c4 + 2] = __floats2bfloat162_rn(r2, r3);
        }
#pragma unroll
        for (int i = 0; i < 2; i++) {
            int u = i * 256 + tid;
            int n = u >> 2, kq = u & 3;
            *(uint4*)&Bth_s[n][kq * 8] = pbh[i];
            *(uint4*)&Btl_s[n][kq * 8] = pbl[i];
        }
        __syncthreads();

        // prefetch next chunk
        if (kc + 1 < C_IN / GK) {
            int k0n = (kc + 1) * GK;
#pragma unroll
            for (int i = 0; i < 4; i++) {
                int flat = i * 256 + tid;
                int row = flat >> 3, c4 = (flat & 7) * 4;
                int gr = m0 + row;
                pa[i] = (gr < NNODES)
                          ? *(const float4*)(A + (size_t)gr * C_IN + k0n + c4)
                          : make_float4(0.f, 0.f, 0.f, 0.f);
            }
#pragma unroll
            for (int i = 0; i < 2; i++) {
                int u = i * 256 + tid;
                int n = u >> 2, kq = u & 3;
                pbh[i] = *(const uint4*)(g_Bth + (size_t)n * C_IN + k0n + kq * 8);
                pbl[i] = *(const uint4*)(g_Btl + (size_t)n * C_IN + k0n + kq * 8);
            }
        }

        // compute: two k16 steps per chunk
#pragma unroll
        for (int s = 0; s < GK; s += 16) {
            uint32_t ah[2][4], al[2][4];
#pragma unroll
            for (int mi = 0; mi < 2; mi++) {
                int r = warp_m * 32 + mi * 16 + g;
                int c = s + t4 * 2;
                ah[mi][0] = *(const uint32_t*)&Ah[r][c];
                ah[mi][1] = *(const uint32_t*)&Ah[r + 8][c];
                ah[mi][2] = *(const uint32_t*)&Ah[r][c + 8];
                ah[mi][3] = *(const uint32_t*)&Ah[r + 8][c + 8];
                al[mi][0] = *(const uint32_t*)&Al[r][c];
                al[mi][1] = *(const uint32_t*)&Al[r + 8][c];
                al[mi][2] = *(const uint32_t*)&Al[r][c + 8];
                al[mi][3] = *(const uint32_t*)&Al[r + 8][c + 8];
            }
            int k0 = s + t4 * 2;
#pragma unroll
            for (int ni = 0; ni < 8; ni++) {
                int n = warp_n * 64 + ni * 8 + g;
                uint32_t bh0 = *(const uint32_t*)&Bth_s[n][k0];
                uint32_t bh1 = *(const uint32_t*)&Bth_s[n][k0 + 8];
                uint32_t bl0 = *(const uint32_t*)&Btl_s[n][k0];
                uint32_t bl1 = *(const uint32_t*)&Btl_s[n][k0 + 8];
#pragma unroll
                for (int mi = 0; mi < 2; mi++) {
                    mma16816(acc[mi][ni], ah[mi], bh0, bh1);   // hi*hi
                    mma16816(acc[mi][ni], ah[mi], bl0, bl1);   // hi*lo
                    mma16816(acc[mi][ni], al[mi], bh0, bh1);   // lo*hi
                }
            }
        }
        __syncthreads();
    }

    // epilogue
#pragma unroll
    for (int mi = 0; mi < 2; mi++) {
#pragma unroll
        for (int ni = 0; ni < 8; ni++) {
            int r = m0 + warp_m * 32 + mi * 16 + g;
            int c = warp_n * 64 + ni * 8 + t4 * 2;
            if (r < NNODES)
                *(float2*)(g_h1 + (size_t)r * C_HID + c) =
                    make_float2(acc[mi][ni][0], acc[mi][ni][1]);
            if (r + 8 < NNODES)
                *(float2*)(g_h1 + (size_t)(r + 8) * C_HID + c) =
                    make_float2(acc[mi][ni][2], acc[mi][ni][3]);
        }
    }
}

// ---------------- attention coefficients layer 1 ----------------
__global__ void att1_kernel(const float* __restrict__ att_src,
                            const float* __restrict__ att_dst) {
    int w = (blockIdx.x * blockDim.x + threadIdx.x) >> 5;
    if (w >= NNODES) return;
    int lane = threadIdx.x & 31;
    float4 hv = *(const float4*)(g_h1 + (size_t)w * 128 + lane * 4);
    float4 s4 = *(const float4*)(att_src + lane * 4);
    float4 d4 = *(const float4*)(att_dst + lane * 4);
    float ps = hv.x * s4.x + hv.y * s4.y + hv.z * s4.z + hv.w * s4.w;
    float pd = hv.x * d4.x + hv.y * d4.y + hv.z * d4.z + hv.w * d4.w;
#pragma unroll
    for (int o = 16; o > 0; o >>= 1) {
        ps += __shfl_xor_sync(0xffffffffu, ps, o);
        pd += __shfl_xor_sync(0xffffffffu, pd, o);
    }
    if (lane == 0) {
        g_asrc1[w] = ps;
        g_adst1[w] = pd;
    }
}

// ---------------- layer-1 softmax aggregation (block per dst node) ---------
// Softmax computed WITHOUT max subtraction (shift-invariant; |e| is O(6)).
__global__ __launch_bounds__(128) void agg1_kernel(const float* __restrict__ bias1) {
    int d = blockIdx.x;
    int t = threadIdx.x;
    int start = g_off[d];
    int cnt = g_deg[d];

    __shared__ float sh[AGG_CAP];
    __shared__ float red[128];

    float adst = g_adst1[d];

    // pass 1: ex = exp(leaky_relu(asrc[s] + adst)); stash + block sum
    float sum = 0.f;
    for (int j = t; j < cnt; j += 128) {
        int s = g_esrc[start + j];
        float e = g_asrc1[s] + adst;
        e = e >= 0.f ? e : NEG_SLOPE * e;
        float ex = __expf(e);
        if (j < AGG_CAP) sh[j] = ex;
        sum += ex;
    }
    red[t] = sum;
    __syncthreads();
#pragma unroll
    for (int o = 64; o > 0; o >>= 1) {
        if (t < o) red[t] += red[t + o];
        __syncthreads();
    }
    float inv = 1.f / (red[0] + 1e-16f);

    // pass 2: channel-parallel weighted accumulation, normalize at end
    float acc = 0.f;
    for (int j = 0; j < cnt; j++) {
        int s = g_esrc[start + j];
        float ex;
        if (j < AGG_CAP) ex = sh[j];
        else {
            float e = g_asrc1[s] + adst;
            e = e >= 0.f ? e : NEG_SLOPE * e;
            ex = __expf(e);
        }
        acc += g_h1[(size_t)s * 128 + t] * ex;
    }
    float v = acc * inv + bias1[t];
    g_out1[(size_t)d * 128 + t] = v > 0.f ? v : 0.f;
}

// ---------------- layer 2 features + attention (warp per node) -------------
__global__ void layer2_kernel(const float* __restrict__ W2,     // [128,6]
                              const float* __restrict__ as2,    // [3,2]
                              const float* __restrict__ ad2) {  // [3,2]
    int w = (blockIdx.x * blockDim.x + threadIdx.x) >> 5;
    if (w >= NNODES) return;
    int lane = threadIdx.x & 31;
    float4 v = *(const float4*)(g_out1 + (size_t)w * 128 + lane * 4);
    float vals[4] = {v.x, v.y, v.z, v.w};
    float p[6] = {0.f, 0.f, 0.f, 0.f, 0.f, 0.f};
#pragma unroll
    for (int i = 0; i < 4; i++) {
        int c = lane * 4 + i;
        const float* wr = W2 + c * 6;
        float val = vals[i];
#pragma unroll
        for (int j = 0; j < 6; j++) p[j] += val * wr[j];
    }
#pragma unroll
    for (int o = 16; o > 0; o >>= 1)
#pragma unroll
        for (int j = 0; j < 6; j++) p[j] += __shfl_xor_sync(0xffffffffu, p[j], o);

    if (lane == 0) {
        float* hp = g_h2 + (size_t)w * 6;
#pragma unroll
        for (int j = 0; j < 6; j++) hp[j] = p[j];
        g_asrc2[w * 3 + 0] = p[0] * as2[0] + p[1] * as2[1];
        g_asrc2[w * 3 + 1] = p[2] * as2[2] + p[3] * as2[3];
        g_asrc2[w * 3 + 2] = p[4] * as2[4] + p[5] * as2[5];
        g_adst2[w * 3 + 0] = p[0] * ad2[0] + p[1] * ad2[1];
        g_adst2[w * 3 + 1] = p[2] * ad2[2] + p[3] * ad2[3];
        g_adst2[w * 3 + 2] = p[4] * ad2[4] + p[5] * ad2[5];
    }
}

// ---------------- layer-2 aggregation + head mean (warp per dst node) ------
__global__ void agg2_kernel(const float* __restrict__ bias2,
                            float* __restrict__ out) {
    int d = (blockIdx.x * blockDim.x + threadIdx.x) >> 5;
    if (d >= NNODES) return;
    int lane = threadIdx.x & 31;
    int start = g_off[d];
    int cnt = g_deg[d];

    float ad0 = g_adst2[d * 3 + 0];
    float ad1 = g_adst2[d * 3 + 1];
    float ad2v = g_adst2[d * 3 + 2];

    // pass 1: denominators (no max subtraction)
    float s0 = 0.f, s1 = 0.f, s2 = 0.f;
    for (int j = lane; j < cnt; j += 32) {
        int s = g_esrc[start + j];
        float e0 = g_asrc2[s * 3 + 0] + ad0; e0 = e0 >= 0.f ? e0 : NEG_SLOPE * e0;
        float e1 = g_asrc2[s * 3 + 1] + ad1; e1 = e1 >= 0.f ? e1 : NEG_SLOPE * e1;
        float e2 = g_asrc2[s * 3 + 2] + ad2v; e2 = e2 >= 0.f ? e2 : NEG_SLOPE * e2;
        s0 += __expf(e0); s1 += __expf(e1); s2 += __expf(e2);
    }
#pragma unroll
    for (int o = 16; o > 0; o >>= 1) {
        s0 += __shfl_xor_sync(0xffffffffu, s0, o);
        s1 += __shfl_xor_sync(0xffffffffu, s1, o);
        s2 += __shfl_xor_sync(0xffffffffu, s2, o);
    }
    float i0 = 1.f / (s0 + 1e-16f);
    float i1 = 1.f / (s1 + 1e-16f);
    float i2 = 1.f / (s2 + 1e-16f);

    // pass 2: unnormalized weighted accumulation
    float acc[6] = {0.f, 0.f, 0.f, 0.f, 0.f, 0.f};
    for (int j = lane; j < cnt; j += 32) {
        int s = g_esrc[start + j];
        float e0 = g_asrc2[s * 3 + 0] + ad0; e0 = e0 >= 0.f ? e0 : NEG_SLOPE * e0;
        float e1 = g_asrc2[s * 3 + 1] + ad1; e1 = e1 >= 0.f ? e1 : NEG_SLOPE * e1;
        float e2 = g_asrc2[s * 3 + 2] + ad2v; e2 = e2 >= 0.f ? e2 : NEG_SLOPE * e2;
        float a0 = __expf(e0);
        float a1 = __expf(e1);
        float a2 = __expf(e2);
        const float* hp = g_h2 + (size_t)s * 6;
        acc[0] += hp[0] * a0; acc[1] += hp[1] * a0;
        acc[2] += hp[2] * a1; acc[3] += hp[3] * a1;
        acc[4] += hp[4] * a2; acc[5] += hp[5] * a2;
    }
#pragma unroll
    for (int o = 16; o > 0; o >>= 1)
#pragma unroll
        for (int j = 0; j < 6; j++) acc[j] += __shfl_xor_sync(0xffffffffu, acc[j], o);

    if (lane == 0) {
        out[d * 2 + 0] = (acc[0] * i0 + acc[2] * i1 + acc[4] * i2) * (1.f / 3.f) + bias2[0];
        out[d * 2 + 1] = (acc[1] * i0 + acc[3] * i1 + acc[5] * i2) * (1.f / 3.f) + bias2[1];
    }
}

// ---------------- launch ----------------
extern "C" void kernel_launch(void* const* d_in, const int* in_sizes, int n_in,
                              void* d_out, int out_size) {
    const float* x   = (const float*)d_in[0];
    const void*  ei  = d_in[1];
    const float* W1  = (const float*)d_in[2];
    const float* as1 = (const float*)d_in[3];
    const float* ad1 = (const float*)d_in[4];
    const float* b1  = (const float*)d_in[5];
    const float* W2  = (const float*)d_in[6];
    const float* as2 = (const float*)d_in[7];
    const float* ad2 = (const float*)d_in[8];
    const float* b2  = (const float*)d_in[9];
    float* out = (float*)d_out;

    detect_kernel<<<1, 1>>>((const unsigned*)ei);

    // CSR build + W1 pre-split (independent of CSR)
    init_deg_kernel<<<(NNODES + 255) / 256, 256>>>();
    count_kernel<<<(NEDGES + 255) / 256, 256>>>(ei);
    convertB_kernel<<<(C_HID * C_IN + 255) / 256, 256>>>(W1);
    csr_partial_kernel<<<SCAN_B, 256>>>();
    csr_scanbase_kernel<<<1, 256>>>();
    csr_offsets_kernel<<<SCAN_B, 256>>>();
    scatter_kernel<<<(TOTE + 255) / 256, 256>>>(ei);

    // Layer 1
    gemm1_bf16_kernel<<<(NNODES + 127) / 128, 256>>>(x);
    att1_kernel<<<(NNODES + 7) / 8, 256>>>(as1, ad1);
    agg1_kernel<<<NNODES, 128>>>(b1);

    // Layer 2
    layer2_kernel<<<(NNODES + 7) / 8, 256>>>(W2, as2, ad2);
    agg2_kernel<<<(NNODES + 7) / 8, 256>>>(b2, out);
}

// round 9
// speedup vs baseline: 2.0747x; 1.2443x over previous
#include <cuda_runtime.h>
#include <cuda_bf16.h>
#include <cstdint>

#define NNODES 50000
#define NEDGES 800000
#define C_IN   512
#define C_HID  128
#define HEADS2 3
#define C_OUT  2
#define TOTE   (NEDGES + NNODES)   // edges + self loops
#define NEG_SLOPE 0.2f
#define SCAN_B ((NNODES + 255) / 256)   // 196
#define W_CAP 96                        // per-warp exp cache (max degree ~60)

// ---------------- scratch (static __device__, no allocations) ----------------
__device__ float g_h1[(size_t)NNODES * C_HID];     // x @ W1
__device__ float g_out1[(size_t)NNODES * C_HID];   // relu(agg1 + b1)
__device__ float g_asrc1[NNODES];
__device__ float g_adst1[NNODES];
__device__ float g_h2[(size_t)NNODES * 6];         // layer2 features [N,3,2]
__device__ float g_asrc2[(size_t)NNODES * 3];
__device__ float g_adst2[(size_t)NNODES * 3];
__device__ int   g_deg[NNODES];
__device__ int   g_off[NNODES];
__device__ int   g_pos[NNODES];
__device__ int   g_esrc[TOTE];                     // src node per edge, grouped by dst
__device__ int   g_is64;                           // edge_index dtype flag
__device__ int   g_bsum[SCAN_B];
__device__ int   g_bbase[SCAN_B];
// W1 pre-split into bf16 hi/lo planes, col-major [n][k]
__device__ __align__(16) __nv_bfloat16 g_Bth[(size_t)C_HID * C_IN];
__device__ __align__(16) __nv_bfloat16 g_Btl[(size_t)C_HID * C_IN];

// ---------------- dtype detection for edge_index ----------------
__global__ void detect_kernel(const unsigned* __restrict__ ei_words) {
    int flag = 1;
    for (int i = 0; i < 64; i++)
        if (ei_words[2 * i + 1] != 0u) { flag = 0; break; }
    g_is64 = flag;
}

__device__ __forceinline__ void load_edge(const void* ei, int e, int& s, int& d) {
    if (g_is64) {
        const long long* p = (const long long*)ei;
        s = (int)p[e];
        d = (int)p[NEDGES + e];
    } else {
        const int* p = (const int*)ei;
        s = p[e];
        d = p[NEDGES + e];
    }
}

// ---------------- CSR build ----------------
__global__ void init_deg_kernel() {
    int i = blockIdx.x * blockDim.x + threadIdx.x;
    if (i < NNODES) g_deg[i] = 1;   // self loop
}

__global__ void count_kernel(const void* __restrict__ ei) {
    int e = blockIdx.x * blockDim.x + threadIdx.x;
    if (e >= NEDGES) return;
    int s, d;
    load_edge(ei, e, s, d);
    atomicAdd(&g_deg[d], 1);
}

// ---- parallel 3-phase scan ----
__global__ void csr_partial_kernel() {
    int i = blockIdx.x * 256 + threadIdx.x;
    int v = (i < NNODES) ? g_deg[i] : 0;
#pragma unroll
    for (int o = 16; o > 0; o >>= 1) v += __shfl_xor_sync(0xffffffffu, v, o);
    __shared__ int ws[8];
    if ((threadIdx.x & 31) == 0) ws[threadIdx.x >> 5] = v;
    __syncthreads();
    if (threadIdx.x == 0) {
        int s = 0;
#pragma unroll
        for (int w = 0; w < 8; w++) s += ws[w];
        g_bsum[blockIdx.x] = s;
    }
}

__global__ void csr_scanbase_kernel() {
    int t = threadIdx.x;
    int lane = t & 31, w = t >> 5;
    int v = (t < SCAN_B) ? g_bsum[t] : 0;
    int incl = v;
#pragma unroll
    for (int o = 1; o < 32; o <<= 1) {
        int u = __shfl_up_sync(0xffffffffu, incl, o);
        if (lane >= o) incl += u;
    }
    __shared__ int ws[8], ws2[8];
    if (lane == 31) ws[w] = incl;
    __syncthreads();
    if (t < 8) {
        int wv = ws[t];
        int wi = wv;
#pragma unroll
        for (int o = 1; o < 8; o <<= 1) {
            int u = __shfl_up_sync(0xffu, wi, o);
            if (t >= o) wi += u;
        }
        ws2[t] = wi - wv;   // exclusive
    }
    __syncthreads();
    if (t < SCAN_B) g_bbase[t] = ws2[w] + incl - v;
}

__global__ void csr_offsets_kernel() {
    int b = blockIdx.x;
    int t = threadIdx.x;
    int i = b * 256 + t;
    int lane = t & 31, w = t >> 5;
    int v = (i < NNODES) ? g_deg[i] : 0;
    int incl = v;
#pragma unroll
    for (int o = 1; o < 32; o <<= 1) {
        int u = __shfl_up_sync(0xffffffffu, incl, o);
        if (lane >= o) incl += u;
    }
    __shared__ int ws[8], ws2[8];
    if (lane == 31) ws[w] = incl;
    __syncthreads();
    if (t < 8) {
        int wv = ws[t];
        int wi = wv;
#pragma unroll
        for (int o = 1; o < 8; o <<= 1) {
            int u = __shfl_up_sync(0xffu, wi, o);
            if (t >= o) wi += u;
        }
        ws2[t] = wi - wv;
    }
    __syncthreads();
    if (i < NNODES) {
        int off = g_bbase[b] + ws2[w] + incl - v;
        g_off[i] = off;
        g_pos[i] = off;
    }
}

__global__ void scatter_kernel(const void* __restrict__ ei) {
    int idx = blockIdx.x * blockDim.x + threadIdx.x;
    if (idx < NEDGES) {
        int s, d;
        load_edge(ei, idx, s, d);
        int p = atomicAdd(&g_pos[d], 1);
        g_esrc[p] = s;
    } else if (idx < TOTE) {
        int i = idx - NEDGES;           // self loop
        int p = atomicAdd(&g_pos[i], 1);
        g_esrc[p] = i;
    }
}

// ---------------- W1 pre-split to bf16 hi/lo, col-major ----------------
__global__ void convertB_kernel(const float* __restrict__ W1) {
    int o = blockIdx.x * 256 + threadIdx.x;     // o = n*512 + k
    if (o >= C_HID * C_IN) return;
    int n = o >> 9, k = o & 511;
    float v = W1[(size_t)k * C_HID + n];
    __nv_bfloat16 h = __float2bfloat16(v);
    g_Bth[o] = h;
    g_Btl[o] = __float2bfloat16(v - __bfloat162float(h));
}

// ---------------- tensor-core GEMM: g_h1 = x @ W1 (bf16 3-term split) -------
#define GK 32           // K chunk
#define AS 40           // A smem row stride (halves)
#define BTS 40          // Bt smem row stride (halves)

__device__ __forceinline__ void mma16816(float* c, const uint32_t* a,
                                         uint32_t b0, uint32_t b1) {
    asm volatile(
        "mma.sync.aligned.m16n8k16.row.col.f32.bf16.bf16.f32 "
        "{%0,%1,%2,%3},{%4,%5,%6,%7},{%8,%9},{%0,%1,%2,%3};"
        : "+f"(c[0]), "+f"(c[1]), "+f"(c[2]), "+f"(c[3])
        : "r"(a[0]), "r"(a[1]), "r"(a[2]), "r"(a[3]), "r"(b0), "r"(b1));
}

__global__ __launch_bounds__(256, 2) void gemm1_bf16_kernel(
    const float* __restrict__ A)   // x  [NNODES, 512]
{
    __shared__ __align__(16) __nv_bfloat16 Ah[128][AS];
    __shared__ __align__(16) __nv_bfloat16 Al[128][AS];
    __shared__ __align__(16) __nv_bfloat16 Bth_s[128][BTS];
    __shared__ __align__(16) __nv_bfloat16 Btl_s[128][BTS];

    const int tid = threadIdx.x;
    const int lane = tid & 31;
    const int wid = tid >> 5;
    const int warp_m = wid & 3;
    const int warp_n = wid >> 2;
    const int g = lane >> 2;
    const int t4 = lane & 3;
    const int m0 = blockIdx.x * 128;

    float acc[2][8][4];
#pragma unroll
    for (int mi = 0; mi < 2; mi++)
#pragma unroll
        for (int ni = 0; ni < 8; ni++)
#pragma unroll
            for (int q = 0; q < 4; q++) acc[mi][ni][q] = 0.f;

    float4 pa[4];
    uint4 pbh[2], pbl[2];

#pragma unroll
    for (int i = 0; i < 4; i++) {
        int flat = i * 256 + tid;
        int row = flat >> 3, c4 = (flat & 7) * 4;
        int gr = m0 + row;
        pa[i] = (gr < NNODES) ? *(const float4*)(A + (size_t)gr * C_IN + c4)
                              : make_float4(0.f, 0.f, 0.f, 0.f);
    }
#pragma unroll
    for (int i = 0; i < 2; i++) {
        int u = i * 256 + tid;
        int n = u >> 2, kq = u & 3;
        pbh[i] = *(const uint4*)(g_Bth + (size_t)n * C_IN + kq * 8);
        pbl[i] = *(const uint4*)(g_Btl + (size_t)n * C_IN + kq * 8);
    }

    for (int kc = 0; kc < C_IN / GK; kc++) {
#pragma unroll
        for (int i = 0; i < 4; i++) {
            int flat = i * 256 + tid;
            int row = flat >> 3, c4 = (flat & 7) * 4;
            float4 v = pa[i];
            __nv_bfloat162 h01 = __floats2bfloat162_rn(v.x, v.y);
            __nv_bfloat162 h23 = __floats2bfloat162_rn(v.z, v.w);
            float r0 = v.x - __bfloat162float(h01.x);
            float r1 = v.y - __bfloat162float(h01.y);
            float r2 = v.z - __bfloat162float(h23.x);
            float r3 = v.w - __bfloat162float(h23.y);
            *(__nv_bfloat162*)&Ah[row][c4]     = h01;
            *(__nv_bfloat162*)&Ah[row][c4 + 2] = h23;
            *(__nv_bfloat162*)&Al[row][c4]     = __floats2bfloat162_rn(r0, r1);
            *(__nv_bfloat162*)&Al[row][c4 + 2] = __floats2bfloat162_rn(r2, r3);
        }
#pragma unroll
        for (int i = 0; i < 2; i++) {
            int u = i * 256 + tid;
            int n = u >> 2, kq = u & 3;
            *(uint4*)&Bth_s[n][kq * 8] = pbh[i];
            *(uint4*)&Btl_s[n][kq * 8] = pbl[i];
        }
        __syncthreads();

        if (kc + 1 < C_IN / GK) {
            int k0n = (kc + 1) * GK;
#pragma unroll
            for (int i = 0; i < 4; i++) {
                int flat = i * 256 + tid;
                int row = flat >> 3, c4 = (flat & 7) * 4;
                int gr = m0 + row;
                pa[i] = (gr < NNODES)
                          ? *(const float4*)(A + (size_t)gr * C_IN + k0n + c4)
                          : make_float4(0.f, 0.f, 0.f, 0.f);
            }
#pragma unroll
            for (int i = 0; i < 2; i++) {
                int u = i * 256 + tid;
                int n = u >> 2, kq = u & 3;
                pbh[i] = *(const uint4*)(g_Bth + (size_t)n * C_IN + k0n + kq * 8);
                pbl[i] = *(const uint4*)(g_Btl + (size_t)n * C_IN + k0n + kq * 8);
            }
        }

#pragma unroll
        for (int s = 0; s < GK; s += 16) {
            uint32_t ah[2][4], al[2][4];
#pragma unroll
            for (int mi = 0; mi < 2; mi++) {
                int r = warp_m * 32 + mi * 16 + g;
                int c = s + t4 * 2;
                ah[mi][0] = *(const uint32_t*)&Ah[r][c];
                ah[mi][1] = *(const uint32_t*)&Ah[r + 8][c];
                ah[mi][2] = *(const uint32_t*)&Ah[r][c + 8];
                ah[mi][3] = *(const uint32_t*)&Ah[r + 8][c + 8];
                al[mi][0] = *(const uint32_t*)&Al[r][c];
                al[mi][1] = *(const uint32_t*)&Al[r + 8][c];
                al[mi][2] = *(const uint32_t*)&Al[r][c + 8];
                al[mi][3] = *(const uint32_t*)&Al[r + 8][c + 8];
            }
            int k0 = s + t4 * 2;
#pragma unroll
            for (int ni = 0; ni < 8; ni++) {
                int n = warp_n * 64 + ni * 8 + g;
                uint32_t bh0 = *(const uint32_t*)&Bth_s[n][k0];
                uint32_t bh1 = *(const uint32_t*)&Bth_s[n][k0 + 8];
                uint32_t bl0 = *(const uint32_t*)&Btl_s[n][k0];
                uint32_t bl1 = *(const uint32_t*)&Btl_s[n][k0 + 8];
#pragma unroll
                for (int mi = 0; mi < 2; mi++) {
                    mma16816(acc[mi][ni], ah[mi], bh0, bh1);   // hi*hi
                    mma16816(acc[mi][ni], ah[mi], bl0, bl1);   // hi*lo
                    mma16816(acc[mi][ni], al[mi], bh0, bh1);   // lo*hi
                }
            }
        }
        __syncthreads();
    }

#pragma unroll
    for (int mi = 0; mi < 2; mi++) {
#pragma unroll
        for (int ni = 0; ni < 8; ni++) {
            int r = m0 + warp_m * 32 + mi * 16 + g;
            int c = warp_n * 64 + ni * 8 + t4 * 2;
            if (r < NNODES)
                *(float2*)(g_h1 + (size_t)r * C_HID + c) =
                    make_float2(acc[mi][ni][0], acc[mi][ni][1]);
            if (r + 8 < NNODES)
                *(float2*)(g_h1 + (size_t)(r + 8) * C_HID + c) =
                    make_float2(acc[mi][ni][2], acc[mi][ni][3]);
        }
    }
}

// ---------------- attention coefficients layer 1 ----------------
__global__ void att1_kernel(const float* __restrict__ att_src,
                            const float* __restrict__ att_dst) {
    int w = (blockIdx.x * blockDim.x + threadIdx.x) >> 5;
    if (w >= NNODES) return;
    int lane = threadIdx.x & 31;
    float4 hv = *(const float4*)(g_h1 + (size_t)w * 128 + lane * 4);
    float4 s4 = *(const float4*)(att_src + lane * 4);
    float4 d4 = *(const float4*)(att_dst + lane * 4);
    float ps = hv.x * s4.x + hv.y * s4.y + hv.z * s4.z + hv.w * s4.w;
    float pd = hv.x * d4.x + hv.y * d4.y + hv.z * d4.z + hv.w * d4.w;
#pragma unroll
    for (int o = 16; o > 0; o >>= 1) {
        ps += __shfl_xor_sync(0xffffffffu, ps, o);
        pd += __shfl_xor_sync(0xffffffffu, pd, o);
    }
    if (lane == 0) {
        g_asrc1[w] = ps;
        g_adst1[w] = pd;
    }
}

// ---------------- layer-1 softmax aggregation (WARP per dst node) ----------
// Lane l owns channels 4l..4l+3 (float4). No max-shift (|e| is O(6)).
__global__ __launch_bounds__(256) void agg1_kernel(const float* __restrict__ bias1) {
    __shared__ float exw[8][W_CAP];
    int warp = threadIdx.x >> 5;
    int lane = threadIdx.x & 31;
    int d = blockIdx.x * 8 + warp;
    if (d >= NNODES) return;

    int start = g_off[d];
    int cnt = g_deg[d];
    float adst = g_adst1[d];

    // pass 1: denominators, cache exp in smem
    float sum = 0.f;
    for (int j = lane; j < cnt; j += 32) {
        int s = g_esrc[start + j];
        float e = g_asrc1[s] + adst;
        e = e >= 0.f ? e : NEG_SLOPE * e;
        float ex = __expf(e);
        if (j < W_CAP) exw[warp][j] = ex;
        sum += ex;
    }
    __syncwarp();
#pragma unroll
    for (int o = 16; o > 0; o >>= 1) sum += __shfl_xor_sync(0xffffffffu, sum, o);
    float inv = 1.f / (sum + 1e-16f);

    // pass 2: weighted row gather (one float4 per lane per edge)
    float4 acc = make_float4(0.f, 0.f, 0.f, 0.f);
    for (int j = 0; j < cnt; j++) {
        int s = g_esrc[start + j];              // uniform across warp (broadcast)
        float ex;
        if (j < W_CAP) ex = exw[warp][j];
        else {
            float e = g_asrc1[s] + adst;
            e = e >= 0.f ? e : NEG_SLOPE * e;
            ex = __expf(e);
        }
        float4 hv = *(const float4*)(g_h1 + (size_t)s * 128 + lane * 4);
        acc.x += hv.x * ex; acc.y += hv.y * ex;
        acc.z += hv.z * ex; acc.w += hv.w * ex;
    }
    float4 b4 = *(const float4*)(bias1 + lane * 4);
    float4 v = make_float4(acc.x * inv + b4.x, acc.y * inv + b4.y,
                           acc.z * inv + b4.z, acc.w * inv + b4.w);
    v.x = v.x > 0.f ? v.x : 0.f;
    v.y = v.y > 0.f ? v.y : 0.f;
    v.z = v.z > 0.f ? v.z : 0.f;
    v.w = v.w > 0.f ? v.w : 0.f;
    *(float4*)(g_out1 + (size_t)d * 128 + lane * 4) = v;
}

// ---------------- layer 2 features + attention (warp per node) -------------
__global__ void layer2_kernel(const float* __restrict__ W2,     // [128,6]
                              const float* __restrict__ as2,    // [3,2]
                              const float* __restrict__ ad2) {  // [3,2]
    int w = (blockIdx.x * blockDim.x + threadIdx.x) >> 5;
    if (w >= NNODES) return;
    int lane = threadIdx.x & 31;
    float4 v = *(const float4*)(g_out1 + (size_t)w * 128 + lane * 4);
    float vals[4] = {v.x, v.y, v.z, v.w};
    float p[6] = {0.f, 0.f, 0.f, 0.f, 0.f, 0.f};
#pragma unroll
    for (int i = 0; i < 4; i++) {
        int c = lane * 4 + i;
        const float* wr = W2 + c * 6;
        float val = vals[i];
#pragma unroll
        for (int j = 0; j < 6; j++) p[j] += val * wr[j];
    }
#pragma unroll
    for (int o = 16; o > 0; o >>= 1)
#pragma unroll
        for (int j = 0; j < 6; j++) p[j] += __shfl_xor_sync(0xffffffffu, p[j], o);

    if (lane == 0) {
        float* hp = g_h2 + (size_t)w * 6;
#pragma unroll
        for (int j = 0; j < 6; j++) hp[j] = p[j];
        g_asrc2[w * 3 + 0] = p[0] * as2[0] + p[1] * as2[1];
        g_asrc2[w * 3 + 1] = p[2] * as2[2] + p[3] * as2[3];
        g_asrc2[w * 3 + 2] = p[4] * as2[4] + p[5] * as2[5];
        g_adst2[w * 3 + 0] = p[0] * ad2[0] + p[1] * ad2[1];
        g_adst2[w * 3 + 1] = p[2] * ad2[2] + p[3] * ad2[3];
        g_adst2[w * 3 + 2] = p[4] * ad2[4] + p[5] * ad2[5];
    }
}

// ---------------- layer-2 aggregation + head mean (warp per dst node) ------
__global__ void agg2_kernel(const float* __restrict__ bias2,
                            float* __restrict__ out) {
    int d = (blockIdx.x * blockDim.x + threadIdx.x) >> 5;
    if (d >= NNODES) return;
    int lane = threadIdx.x & 31;
    int start = g_off[d];
    int cnt = g_deg[d];

    float ad0 = g_adst2[d * 3 + 0];
    float ad1 = g_adst2[d * 3 + 1];
    float ad2v = g_adst2[d * 3 + 2];

    float s0 = 0.f, s1 = 0.f, s2 = 0.f;
    for (int j = lane; j < cnt; j += 32) {
        int s = g_esrc[start + j];
        float e0 = g_asrc2[s * 3 + 0] + ad0; e0 = e0 >= 0.f ? e0 : NEG_SLOPE * e0;
        float e1 = g_asrc2[s * 3 + 1] + ad1; e1 = e1 >= 0.f ? e1 : NEG_SLOPE * e1;
        float e2 = g_asrc2[s * 3 + 2] + ad2v; e2 = e2 >= 0.f ? e2 : NEG_SLOPE * e2;
        s0 += __expf(e0); s1 += __expf(e1); s2 += __expf(e2);
    }
#pragma unroll
    for (int o = 16; o > 0; o >>= 1) {
        s0 += __shfl_xor_sync(0xffffffffu, s0, o);
        s1 += __shfl_xor_sync(0xffffffffu, s1, o);
        s2 += __shfl_xor_sync(0xffffffffu, s2, o);
    }
    float i0 = 1.f / (s0 + 1e-16f);
    float i1 = 1.f / (s1 + 1e-16f);
    float i2 = 1.f / (s2 + 1e-16f);

    float acc[6] = {0.f, 0.f, 0.f, 0.f, 0.f, 0.f};
    for (int j = lane; j < cnt; j += 32) {
        int s = g_esrc[start + j];
        float e0 = g_asrc2[s * 3 + 0] + ad0; e0 = e0 >= 0.f ? e0 : NEG_SLOPE * e0;
        float e1 = g_asrc2[s * 3 + 1] + ad1; e1 = e1 >= 0.f ? e1 : NEG_SLOPE * e1;
        float e2 = g_asrc2[s * 3 + 2] + ad2v; e2 = e2 >= 0.f ? e2 : NEG_SLOPE * e2;
        float a0 = __expf(e0);
        float a1 = __expf(e1);
        float a2 = __expf(e2);
        const float* hp = g_h2 + (size_t)s * 6;
        acc[0] += hp[0] * a0; acc[1] += hp[1] * a0;
        acc[2] += hp[2] * a1; acc[3] += hp[3] * a1;
        acc[4] += hp[4] * a2; acc[5] += hp[5] * a2;
    }
#pragma unroll
    for (int o = 16; o > 0; o >>= 1)
#pragma unroll
        for (int j = 0; j < 6; j++) acc[j] += __shfl_xor_sync(0xffffffffu, acc[j], o);

    if (lane == 0) {
        out[d * 2 + 0] = (acc[0] * i0 + acc[2] * i1 + acc[4] * i2) * (1.f / 3.f) + bias2[0];
        out[d * 2 + 1] = (acc[1] * i0 + acc[3] * i1 + acc[5] * i2) * (1.f / 3.f) + bias2[1];
    }
}

// ---------------- launch ----------------
extern "C" void kernel_launch(void* const* d_in, const int* in_sizes, int n_in,
                              void* d_out, int out_size) {
    const float* x   = (const float*)d_in[0];
    const void*  ei  = d_in[1];
    const float* W1  = (const float*)d_in[2];
    const float* as1 = (const float*)d_in[3];
    const float* ad1 = (const float*)d_in[4];
    const float* b1  = (const float*)d_in[5];
    const float* W2  = (const float*)d_in[6];
    const float* as2 = (const float*)d_in[7];
    const float* ad2 = (const float*)d_in[8];
    const float* b2  = (const float*)d_in[9];
    float* out = (float*)d_out;

    detect_kernel<<<1, 1>>>((const unsigned*)ei);

    // CSR build + W1 pre-split (independent of CSR)
    init_deg_kernel<<<(NNODES + 255) / 256, 256>>>();
    count_kernel<<<(NEDGES + 255) / 256, 256>>>(ei);
    convertB_kernel<<<(C_HID * C_IN + 255) / 256, 256>>>(W1);
    csr_partial_kernel<<<SCAN_B, 256>>>();
    csr_scanbase_kernel<<<1, 256>>>();
    csr_offsets_kernel<<<SCAN_B, 256>>>();
    scatter_kernel<<<(TOTE + 255) / 256, 256>>>(ei);

    // Layer 1
    gemm1_bf16_kernel<<<(NNODES + 127) / 128, 256>>>(x);
    att1_kernel<<<(NNODES + 7) / 8, 256>>>(as1, ad1);
    agg1_kernel<<<(NNODES + 7) / 8, 256>>>(b1);

    // Layer 2
    layer2_kernel<<<(NNODES + 7) / 8, 256>>>(W2, as2, ad2);
    agg2_kernel<<<(NNODES + 7) / 8, 256>>>(b2, out);
}

// round 11
// speedup vs baseline: 2.5032x; 1.2065x over previous
#include <cuda_runtime.h>
#include <cuda_bf16.h>
#include <cstdint>

#define NNODES 50000
#define NEDGES 800000
#define C_IN   512
#define C_HID  128
#define HEADS2 3
#define C_OUT  2
#define TOTE   (NEDGES + NNODES)   // edges + self loops
#define NEG_SLOPE 0.2f
#define SCAN_B ((NNODES + 255) / 256)   // 196
#define W_CAP 96                        // per-warp exp cache (max degree ~60)

// ---------------- scratch (static __device__, no allocations) ----------------
__device__ float g_h1[(size_t)NNODES * C_HID];     // x @ W1
__device__ float g_asrc1[NNODES];
__device__ float g_adst1[NNODES];
__device__ float g_h2[(size_t)NNODES * 6];         // layer2 features [N,3,2]
__device__ float g_asrc2[(size_t)NNODES * 3];
__device__ float g_adst2[(size_t)NNODES * 3];
__device__ int   g_deg[NNODES];
__device__ int   g_off[NNODES];
__device__ int   g_pos[NNODES];
__device__ int   g_esrc[TOTE];                     // src node per edge, grouped by dst
__device__ int   g_is64;                           // edge_index dtype flag
__device__ int   g_bsum[SCAN_B];
__device__ int   g_bbase[SCAN_B];
// W1 pre-split into bf16 hi/lo planes, col-major [n][k]
__device__ __align__(16) __nv_bfloat16 g_Bth[(size_t)C_HID * C_IN];
__device__ __align__(16) __nv_bfloat16 g_Btl[(size_t)C_HID * C_IN];

// ---------------- dtype detection for edge_index ----------------
__global__ void detect_kernel(const unsigned* __restrict__ ei_words) {
    int flag = 1;
    for (int i = 0; i < 64; i++)
        if (ei_words[2 * i + 1] != 0u) { flag = 0; break; }
    g_is64 = flag;
}

__device__ __forceinline__ void load_edge(const void* ei, int e, int& s, int& d) {
    if (g_is64) {
        const long long* p = (const long long*)ei;
        s = (int)p[e];
        d = (int)p[NEDGES + e];
    } else {
        const int* p = (const int*)ei;
        s = p[e];
        d = p[NEDGES + e];
    }
}

// ---------------- CSR build ----------------
__global__ void init_deg_kernel() {
    int i = blockIdx.x * blockDim.x + threadIdx.x;
    if (i < NNODES) g_deg[i] = 1;   // self loop
}

__global__ void count_kernel(const void* __restrict__ ei) {
    int e = blockIdx.x * blockDim.x + threadIdx.x;
    if (e >= NEDGES) return;
    int s, d;
    load_edge(ei, e, s, d);
    atomicAdd(&g_deg[d], 1);
}

// ---- parallel 3-phase scan ----
__global__ void csr_partial_kernel() {
    int i = blockIdx.x * 256 + threadIdx.x;
    int v = (i < NNODES) ? g_deg[i] : 0;
#pragma unroll
    for (int o = 16; o > 0; o >>= 1) v += __shfl_xor_sync(0xffffffffu, v, o);
    __shared__ int ws[8];
    if ((threadIdx.x & 31) == 0) ws[threadIdx.x >> 5] = v;
    __syncthreads();
    if (threadIdx.x == 0) {
        int s = 0;
#pragma unroll
        for (int w = 0; w < 8; w++) s += ws[w];
        g_bsum[blockIdx.x] = s;
    }
}

__global__ void csr_scanbase_kernel() {
    int t = threadIdx.x;
    int lane = t & 31, w = t >> 5;
    int v = (t < SCAN_B) ? g_bsum[t] : 0;
    int incl = v;
#pragma unroll
    for (int o = 1; o < 32; o <<= 1) {
        int u = __shfl_up_sync(0xffffffffu, incl, o);
        if (lane >= o) incl += u;
    }
    __shared__ int ws[8], ws2[8];
    if (lane == 31) ws[w] = incl;
    __syncthreads();
    if (t < 8) {
        int wv = ws[t];
        int wi = wv;
#pragma unroll
        for (int o = 1; o < 8; o <<= 1) {
            int u = __shfl_up_sync(0xffu, wi, o);
            if (t >= o) wi += u;
        }
        ws2[t] = wi - wv;   // exclusive
    }
    __syncthreads();
    if (t < SCAN_B) g_bbase[t] = ws2[w] + incl - v;
}

__global__ void csr_offsets_kernel() {
    int b = blockIdx.x;
    int t = threadIdx.x;
    int i = b * 256 + t;
    int lane = t & 31, w = t >> 5;
    int v = (i < NNODES) ? g_deg[i] : 0;
    int incl = v;
#pragma unroll
    for (int o = 1; o < 32; o <<= 1) {
        int u = __shfl_up_sync(0xffffffffu, incl, o);
        if (lane >= o) incl += u;
    }
    __shared__ int ws[8], ws2[8];
    if (lane == 31) ws[w] = incl;
    __syncthreads();
    if (t < 8) {
        int wv = ws[t];
        int wi = wv;
#pragma unroll
        for (int o = 1; o < 8; o <<= 1) {
            int u = __shfl_up_sync(0xffu, wi, o);
            if (t >= o) wi += u;
        }
        ws2[t] = wi - wv;
    }
    __syncthreads();
    if (i < NNODES) {
        int off = g_bbase[b] + ws2[w] + incl - v;
        g_off[i] = off;
        g_pos[i] = off;
    }
}

__global__ void scatter_kernel(const void* __restrict__ ei) {
    int idx = blockIdx.x * blockDim.x + threadIdx.x;
    if (idx < NEDGES) {
        int s, d;
        load_edge(ei, idx, s, d);
        int p = atomicAdd(&g_pos[d], 1);
        g_esrc[p] = s;
    } else if (idx < TOTE) {
        int i = idx - NEDGES;           // self loop
        int p = atomicAdd(&g_pos[i], 1);
        g_esrc[p] = i;
    }
}

// ---------------- W1 pre-split to bf16 hi/lo, col-major ----------------
__global__ void convertB_kernel(const float* __restrict__ W1) {
    int o = blockIdx.x * 256 + threadIdx.x;     // o = n*512 + k
    if (o >= C_HID * C_IN) return;
    int n = o >> 9, k = o & 511;
    float v = W1[(size_t)k * C_HID + n];
    __nv_bfloat16 h = __float2bfloat16(v);
    g_Bth[o] = h;
    g_Btl[o] = __float2bfloat16(v - __bfloat162float(h));
}

// ---------------- tensor-core GEMM: g_h1 = x @ W1 (bf16 3-term split) -------
// Fused epilogue: also computes g_asrc1/g_adst1 = h1 . att_{src,dst}.
#define GK 32           // K chunk
#define AS 40           // A smem row stride (halves)
#define BTS 40          // Bt smem row stride (halves)

__device__ __forceinline__ void mma16816(float* c, const uint32_t* a,
                                         uint32_t b0, uint32_t b1) {
    asm volatile(
        "mma.sync.aligned.m16n8k16.row.col.f32.bf16.bf16.f32 "
        "{%0,%1,%2,%3},{%4,%5,%6,%7},{%8,%9},{%0,%1,%2,%3};"
        : "+f"(c[0]), "+f"(c[1]), "+f"(c[2]), "+f"(c[3])
        : "r"(a[0]), "r"(a[1]), "r"(a[2]), "r"(a[3]), "r"(b0), "r"(b1));
}

__global__ __launch_bounds__(256, 2) void gemm1_bf16_kernel(
    const float* __restrict__ A,        // x  [NNODES, 512]
    const float* __restrict__ att_src,  // [128]
    const float* __restrict__ att_dst)  // [128]
{
    __shared__ __align__(16) __nv_bfloat16 Ah[128][AS];
    __shared__ __align__(16) __nv_bfloat16 Al[128][AS];
    __shared__ __align__(16) __nv_bfloat16 Bth_s[128][BTS];
    __shared__ __align__(16) __nv_bfloat16 Btl_s[128][BTS];
    __shared__ float sAs[128], sAd[128];
    __shared__ float sPs[128][2], sPd[128][2];

    const int tid = threadIdx.x;
    const int lane = tid & 31;
    const int wid = tid >> 5;
    const int warp_m = wid & 3;
    const int warp_n = wid >> 2;
    const int g = lane >> 2;
    const int t4 = lane & 3;
    const int m0 = blockIdx.x * 128;

    if (tid < 128) {
        sAs[tid] = att_src[tid];
        sAd[tid] = att_dst[tid];
    }

    float acc[2][8][4];
#pragma unroll
    for (int mi = 0; mi < 2; mi++)
#pragma unroll
        for (int ni = 0; ni < 8; ni++)
#pragma unroll
            for (int q = 0; q < 4; q++) acc[mi][ni][q] = 0.f;

    float4 pa[4];
    uint4 pbh[2], pbl[2];

#pragma unroll
    for (int i = 0; i < 4; i++) {
        int flat = i * 256 + tid;
        int row = flat >> 3, c4 = (flat & 7) * 4;
        int gr = m0 + row;
        pa[i] = (gr < NNODES) ? *(const float4*)(A + (size_t)gr * C_IN + c4)
                              : make_float4(0.f, 0.f, 0.f, 0.f);
    }
#pragma unroll
    for (int i = 0; i < 2; i++) {
        int u = i * 256 + tid;
        int n = u >> 2, kq = u & 3;
        pbh[i] = *(const uint4*)(g_Bth + (size_t)n * C_IN + kq * 8);
        pbl[i] = *(const uint4*)(g_Btl + (size_t)n * C_IN + kq * 8);
    }

    for (int kc = 0; kc < C_IN / GK; kc++) {
#pragma unroll
        for (int i = 0; i < 4; i++) {
            int flat = i * 256 + tid;
            int row = flat >> 3, c4 = (flat & 7) * 4;
            float4 v = pa[i];
            __nv_bfloat162 h01 = __floats2bfloat162_rn(v.x, v.y);
            __nv_bfloat162 h23 = __floats2bfloat162_rn(v.z, v.w);
            float r0 = v.x - __bfloat162float(h01.x);
            float r1 = v.y - __bfloat162float(h01.y);
            float r2 = v.z - __bfloat162float(h23.x);
            float r3 = v.w - __bfloat162float(h23.y);
            *(__nv_bfloat162*)&Ah[row][c4]     = h01;
            *(__nv_bfloat162*)&Ah[row][c4 + 2] = h23;
            *(__nv_bfloat162*)&Al[row][c4]     = __floats2bfloat162_rn(r0, r1);
            *(__nv_bfloat162*)&Al[row][c4 + 2] = __floats2bfloat162_rn(r2, r3);
        }
#pragma unroll
        for (int i = 0; i < 2; i++) {
            int u = i * 256 + tid;
            int n = u >> 2, kq = u & 3;
            *(uint4*)&Bth_s[n][kq * 8] = pbh[i];
            *(uint4*)&Btl_s[n][kq * 8] = pbl[i];
        }
        __syncthreads();

        if (kc + 1 < C_IN / GK) {
            int k0n = (kc + 1) * GK;
#pragma unroll
            for (int i = 0; i < 4; i++) {
                int flat = i * 256 + tid;
                int row = flat >> 3, c4 = (flat & 7) * 4;
                int gr = m0 + row;
                pa[i] = (gr < NNODES)
                          ? *(const float4*)(A + (size_t)gr * C_IN + k0n + c4)
                          : make_float4(0.f, 0.f, 0.f, 0.f);
            }
#pragma unroll
            for (int i = 0; i < 2; i++) {
                int u = i * 256 + tid;
                int n = u >> 2, kq = u & 3;
                pbh[i] = *(const uint4*)(g_Bth + (size_t)n * C_IN + k0n + kq * 8);
                pbl[i] = *(const uint4*)(g_Btl + (size_t)n * C_IN + k0n + kq * 8);
            }
        }

#pragma unroll
        for (int s = 0; s < GK; s += 16) {
            uint32_t ah[2][4], al[2][4];
#pragma unroll
            for (int mi = 0; mi < 2; mi++) {
                int r = warp_m * 32 + mi * 16 + g;
                int c = s + t4 * 2;
                ah[mi][0] = *(const uint32_t*)&Ah[r][c];
                ah[mi][1] = *(const uint32_t*)&Ah[r + 8][c];
                ah[mi][2] = *(const uint32_t*)&Ah[r][c + 8];
                ah[mi][3] = *(const uint32_t*)&Ah[r + 8][c + 8];
                al[mi][0] = *(const uint32_t*)&Al[r][c];
                al[mi][1] = *(const uint32_t*)&Al[r + 8][c];
                al[mi][2] = *(const uint32_t*)&Al[r][c + 8];
                al[mi][3] = *(const uint32_t*)&Al[r + 8][c + 8];
            }
            int k0 = s + t4 * 2;
#pragma unroll
            for (int ni = 0; ni < 8; ni++) {
                int n = warp_n * 64 + ni * 8 + g;
                uint32_t bh0 = *(const uint32_t*)&Bth_s[n][k0];
                uint32_t bh1 = *(const uint32_t*)&Bth_s[n][k0 + 8];
                uint32_t bl0 = *(const uint32_t*)&Btl_s[n][k0];
                uint32_t bl1 = *(const uint32_t*)&Btl_s[n][k0 + 8];
#pragma unroll
                for (int mi = 0; mi < 2; mi++) {
                    mma16816(acc[mi][ni], ah[mi], bh0, bh1);   // hi*hi
                    mma16816(acc[mi][ni], ah[mi], bl0, bl1);   // hi*lo
                    mma16816(acc[mi][ni], al[mi], bh0, bh1);   // lo*hi
                }
            }
        }
        __syncthreads();
    }

    // ---- epilogue: store h1 + fused attention dot products ----
#pragma unroll
    for (int mi = 0; mi < 2; mi++) {
        float psA = 0.f, psB = 0.f, pdA = 0.f, pdB = 0.f;
#pragma unroll
        for (int ni = 0; ni < 8; ni++) {
            int r = m0 + warp_m * 32 + mi * 16 + g;
            int c = warp_n * 64 + ni * 8 + t4 * 2;
            if (r < NNODES)
                *(float2*)(g_h1 + (size_t)r * C_HID + c) =
                    make_float2(acc[mi][ni][0], acc[mi][ni][1]);
            if (r + 8 < NNODES)
                *(float2*)(g_h1 + (size_t)(r + 8) * C_HID + c) =
                    make_float2(acc[mi][ni][2], acc[mi][ni][3]);
            float a0 = sAs[c], a1 = sAs[c + 1];
            float d0 = sAd[c], d1 = sAd[c + 1];
            psA += acc[mi][ni][0] * a0 + acc[mi][ni][1] * a1;
            psB += acc[mi][ni][2] * a0 + acc[mi][ni][3] * a1;
            pdA += acc[mi][ni][0] * d0 + acc[mi][ni][1] * d1;
            pdB += acc[mi][ni][2] * d0 + acc[mi][ni][3] * d1;
        }
#pragma unroll
        for (int o = 1; o <= 2; o <<= 1) {
            psA += __shfl_xor_sync(0xffffffffu, psA, o);
            psB += __shfl_xor_sync(0xffffffffu, psB, o);
            pdA += __shfl_xor_sync(0xffffffffu, pdA, o);
            pdB += __shfl_xor_sync(0xffffffffu, pdB, o);
        }
        if (t4 == 0) {
            int rl = warp_m * 32 + mi * 16 + g;
            sPs[rl][warp_n] = psA;  sPs[rl + 8][warp_n] = psB;
            sPd[rl][warp_n] = pdA;  sPd[rl + 8][warp_n] = pdB;
        }
    }
    __syncthreads();
    if (tid < 128) {
        int r = m0 + tid;
        if (r < NNODES) {
            g_asrc1[r] = sPs[tid][0] + sPs[tid][1];
            g_adst1[r] = sPd[tid][0] + sPd[tid][1];
        }
    }
}

// ---------------- layer-1 aggregation + FUSED layer-2 projection -----------
// Warp per dst node. Lane l owns channels 4l..4l+3. No max-shift softmax.
// After aggregation: v = relu(agg+b1); p = v @ W2 (warp-reduced);
// writes g_h2 and layer-2 attention scalars directly (g_out1 eliminated).
__global__ __launch_bounds__(256) void agg1_kernel(const float* __restrict__ bias1,
                                                   const float* __restrict__ W2,
                                                   const float* __restrict__ as2,
                                                   const float* __restrict__ ad2) {
    __shared__ float exw[8][W_CAP];
    __shared__ float sW2[C_HID * 6];
    __shared__ float sa2[6], sd2[6];

    int tid = threadIdx.x;
    for (int i = tid; i < C_HID * 6; i += 256) sW2[i] = W2[i];
    if (tid < 6) { sa2[tid] = as2[tid]; sd2[tid] = ad2[tid]; }
    __syncthreads();

    int warp = tid >> 5;
    int lane = tid & 31;
    int d = blockIdx.x * 8 + warp;
    if (d >= NNODES) return;

    int start = g_off[d];
    int cnt = g_deg[d];
    float adst = g_adst1[d];

    // pass 1: denominators, cache exp in smem
    float sum = 0.f;
    for (int j = lane; j < cnt; j += 32) {
        int s = g_esrc[start + j];
        float e = g_asrc1[s] + adst;
        e = e >= 0.f ? e : NEG_SLOPE * e;
        float ex = __expf(e);
        if (j < W_CAP) exw[warp][j] = ex;
        sum += ex;
    }
    __syncwarp();
#pragma unroll
    for (int o = 16; o > 0; o >>= 1) sum += __shfl_xor_sync(0xffffffffu, sum, o);
    float inv = 1.f / (sum + 1e-16f);

    // pass 2: weighted row gather
    float4 acc = make_float4(0.f, 0.f, 0.f, 0.f);
    for (int j = 0; j < cnt; j++) {
        int s = g_esrc[start + j];
        float ex;
        if (j < W_CAP) ex = exw[warp][j];
        else {
            float e = g_asrc1[s] + adst;
            e = e >= 0.f ? e : NEG_SLOPE * e;
            ex = __expf(e);
        }
        float4 hv = *(const float4*)(g_h1 + (size_t)s * 128 + lane * 4);
        acc.x += hv.x * ex; acc.y += hv.y * ex;
        acc.z += hv.z * ex; acc.w += hv.w * ex;
    }
    float4 b4 = *(const float4*)(bias1 + lane * 4);
    float vx = acc.x * inv + b4.x; vx = vx > 0.f ? vx : 0.f;
    float vy = acc.y * inv + b4.y; vy = vy > 0.f ? vy : 0.f;
    float vz = acc.z * inv + b4.z; vz = vz > 0.f ? vz : 0.f;
    float vw = acc.w * inv + b4.w; vw = vw > 0.f ? vw : 0.f;

    // fused layer-2 projection: p[6] = v(128) @ W2(128x6)
    float p[6];
    {
        int c = lane * 4;
        const float* w0 = &sW2[(c + 0) * 6];
        const float* w1 = &sW2[(c + 1) * 6];
        const float* w2r = &sW2[(c + 2) * 6];
        const float* w3 = &sW2[(c + 3) * 6];
#pragma unroll
        for (int j = 0; j < 6; j++)
            p[j] = vx * w0[j] + vy * w1[j] + vz * w2r[j] + vw * w3[j];
    }
#pragma unroll
    for (int o = 16; o > 0; o >>= 1)
#pragma unroll
        for (int j = 0; j < 6; j++) p[j] += __shfl_xor_sync(0xffffffffu, p[j], o);

    if (lane == 0) {
        float* hp = g_h2 + (size_t)d * 6;
#pragma unroll
        for (int j = 0; j < 6; j++) hp[j] = p[j];
        g_asrc2[d * 3 + 0] = p[0] * sa2[0] + p[1] * sa2[1];
        g_asrc2[d * 3 + 1] = p[2] * sa2[2] + p[3] * sa2[3];
        g_asrc2[d * 3 + 2] = p[4] * sa2[4] + p[5] * sa2[5];
        g_adst2[d * 3 + 0] = p[0] * sd2[0] + p[1] * sd2[1];
        g_adst2[d * 3 + 1] = p[2] * sd2[2] + p[3] * sd2[3];
        g_adst2[d * 3 + 2] = p[4] * sd2[4] + p[5] * sd2[5];
    }
}

// ---------------- layer-2 aggregation + head mean (warp per dst node) ------
__global__ __launch_bounds__(256) void agg2_kernel(const float* __restrict__ bias2,
                                                   float* __restrict__ out) {
    __shared__ float ca0[8][W_CAP], ca1[8][W_CAP], ca2[8][W_CAP];
    int warp = threadIdx.x >> 5;
    int lane = threadIdx.x & 31;
    int d = blockIdx.x * 8 + warp;
    if (d >= NNODES) return;

    int start = g_off[d];
    int cnt = g_deg[d];

    float ad0 = g_adst2[d * 3 + 0];
    float ad1 = g_adst2[d * 3 + 1];
    float ad2v = g_adst2[d * 3 + 2];

    // pass 1: denominators + cache exps
    float s0 = 0.f, s1 = 0.f, s2 = 0.f;
    for (int j = lane; j < cnt; j += 32) {
        int s = g_esrc[start + j];
        float e0 = g_asrc2[s * 3 + 0] + ad0; e0 = e0 >= 0.f ? e0 : NEG_SLOPE * e0;
        float e1 = g_asrc2[s * 3 + 1] + ad1; e1 = e1 >= 0.f ? e1 : NEG_SLOPE * e1;
        float e2 = g_asrc2[s * 3 + 2] + ad2v; e2 = e2 >= 0.f ? e2 : NEG_SLOPE * e2;
        float a0 = __expf(e0), a1 = __expf(e1), a2 = __expf(e2);
        if (j < W_CAP) { ca0[warp][j] = a0; ca1[warp][j] = a1; ca2[warp][j] = a2; }
        s0 += a0; s1 += a1; s2 += a2;
    }
    __syncwarp();
#pragma unroll
    for (int o = 16; o > 0; o >>= 1) {
        s0 += __shfl_xor_sync(0xffffffffu, s0, o);
        s1 += __shfl_xor_sync(0xffffffffu, s1, o);
        s2 += __shfl_xor_sync(0xffffffffu, s2, o);
    }
    float i0 = 1.f / (s0 + 1e-16f);
    float i1 = 1.f / (s1 + 1e-16f);
    float i2 = 1.f / (s2 + 1e-16f);

    // pass 2: weighted accumulation using cached exps
    float acc[6] = {0.f, 0.f, 0.f, 0.f, 0.f, 0.f};
    for (int j = lane; j < cnt; j += 32) {
        int s = g_esrc[start + j];
        float a0, a1, a2;
        if (j < W_CAP) { a0 = ca0[warp][j]; a1 = ca1[warp][j]; a2 = ca2[warp][j]; }
        else {
            float e0 = g_asrc2[s * 3 + 0] + ad0; e0 = e0 >= 0.f ? e0 : NEG_SLOPE * e0;
            float e1 = g_asrc2[s * 3 + 1] + ad1; e1 = e1 >= 0.f ? e1 : NEG_SLOPE * e1;
            float e2 = g_asrc2[s * 3 + 2] + ad2v; e2 = e2 >= 0.f ? e2 : NEG_SLOPE * e2;
            a0 = __expf(e0); a1 = __expf(e1); a2 = __expf(e2);
        }
        const float* hp = g_h2 + (size_t)s * 6;
        acc[0] += hp[0] * a0; acc[1] += hp[1] * a0;
        acc[2] += hp[2] * a1; acc[3] += hp[3] * a1;
        acc[4] += hp[4] * a2; acc[5] += hp[5] * a2;
    }
#pragma unroll
    for (int o = 16; o > 0; o >>= 1)
#pragma unroll
        for (int j = 0; j < 6; j++) acc[j] += __shfl_xor_sync(0xffffffffu, acc[j], o);

    if (lane == 0) {
        out[d * 2 + 0] = (acc[0] * i0 + acc[2] * i1 + acc[4] * i2) * (1.f / 3.f) + bias2[0];
        out[d * 2 + 1] = (acc[1] * i0 + acc[3] * i1 + acc[5] * i2) * (1.f / 3.f) + bias2[1];
    }
}

// ---------------- launch ----------------
extern "C" void kernel_launch(void* const* d_in, const int* in_sizes, int n_in,
                              void* d_out, int out_size) {
    const float* x   = (const float*)d_in[0];
    const void*  ei  = d_in[1];
    const float* W1  = (const float*)d_in[2];
    const float* as1 = (const float*)d_in[3];
    const float* ad1 = (const float*)d_in[4];
    const float* b1  = (const float*)d_in[5];
    const float* W2  = (const float*)d_in[6];
    const float* as2 = (const float*)d_in[7];
    const float* ad2 = (const float*)d_in[8];
    const float* b2  = (const float*)d_in[9];
    float* out = (float*)d_out;

    detect_kernel<<<1, 1>>>((const unsigned*)ei);

    // CSR build + W1 pre-split (independent of CSR)
    init_deg_kernel<<<(NNODES + 255) / 256, 256>>>();
    count_kernel<<<(NEDGES + 255) / 256, 256>>>(ei);
    convertB_kernel<<<(C_HID * C_IN + 255) / 256, 256>>>(W1);
    csr_partial_kernel<<<SCAN_B, 256>>>();
    csr_scanbase_kernel<<<1, 256>>>();
    csr_offsets_kernel<<<SCAN_B, 256>>>();
    scatter_kernel<<<(TOTE + 255) / 256, 256>>>(ei);

    // Layer 1 (GEMM with fused attention epilogue)
    gemm1_bf16_kernel<<<(NNODES + 127) / 128, 256>>>(x, as1, ad1);
    agg1_kernel<<<(NNODES + 7) / 8, 256>>>(b1, W2, as2, ad2);

    // Layer 2
    agg2_kernel<<<(NNODES + 7) / 8, 256>>>(b2, out);
}

// round 14
// speedup vs baseline: 2.8055x; 1.1208x over previous
#include <cuda_runtime.h>
#include <cuda_bf16.h>
#include <cstdint>

#define NNODES 50000
#define NEDGES 800000
#define C_IN   512
#define C_HID  128
#define HEADS2 3
#define C_OUT  2
#define TOTE   (NEDGES + NNODES)   // edges + self loops
#define NEG_SLOPE 0.2f
#define SCAN_B ((NNODES + 255) / 256)   // 196
#define W_CAP 96                        // per-warp exp cache (max degree ~60)

// ---------------- scratch (static __device__, no allocations) ----------------
__device__ float g_h1[(size_t)NNODES * C_HID];     // x @ W1
__device__ float g_asrc1[NNODES];
__device__ float g_adst1[NNODES];
__device__ float g_h2[(size_t)NNODES * 6];         // layer2 features [N,3,2]
__device__ float g_asrc2[(size_t)NNODES * 3];
__device__ float g_adst2[(size_t)NNODES * 3];
__device__ int   g_deg[NNODES];
__device__ int   g_off[NNODES];
__device__ int   g_pos[NNODES];
__device__ int   g_esrc[TOTE];                     // src node per edge, grouped by dst
__device__ int   g_is64;                           // edge_index dtype flag
__device__ int   g_bsum[SCAN_B];
__device__ int   g_bbase[SCAN_B];
// W1 pre-split into bf16 hi/lo planes, col-major [n][k]
__device__ __align__(16) __nv_bfloat16 g_Bth[(size_t)C_HID * C_IN];
__device__ __align__(16) __nv_bfloat16 g_Btl[(size_t)C_HID * C_IN];

// ---------------- dtype detection for edge_index ----------------
__global__ void detect_kernel(const unsigned* __restrict__ ei_words) {
    int flag = 1;
    for (int i = 0; i < 64; i++)
        if (ei_words[2 * i + 1] != 0u) { flag = 0; break; }
    g_is64 = flag;
}

__device__ __forceinline__ void load_edge(const void* ei, int e, int& s, int& d) {
    if (g_is64) {
        const long long* p = (const long long*)ei;
        s = (int)p[e];
        d = (int)p[NEDGES + e];
    } else {
        const int* p = (const int*)ei;
        s = p[e];
        d = p[NEDGES + e];
    }
}

// ---------------- CSR build ----------------
__global__ void init_deg_kernel() {
    int i = blockIdx.x * blockDim.x + threadIdx.x;
    if (i < NNODES) g_deg[i] = 1;   // self loop
}

__global__ void count_kernel(const void* __restrict__ ei) {
    int e = blockIdx.x * blockDim.x + threadIdx.x;
    if (e >= NEDGES) return;
    int s, d;
    load_edge(ei, e, s, d);
    atomicAdd(&g_deg[d], 1);
}

// ---- parallel 3-phase scan ----
__global__ void csr_partial_kernel() {
    int i = blockIdx.x * 256 + threadIdx.x;
    int v = (i < NNODES) ? g_deg[i] : 0;
#pragma unroll
    for (int o = 16; o > 0; o >>= 1) v += __shfl_xor_sync(0xffffffffu, v, o);
    __shared__ int ws[8];
    if ((threadIdx.x & 31) == 0) ws[threadIdx.x >> 5] = v;
    __syncthreads();
    if (threadIdx.x == 0) {
        int s = 0;
#pragma unroll
        for (int w = 0; w < 8; w++) s += ws[w];
        g_bsum[blockIdx.x] = s;
    }
}

__global__ void csr_scanbase_kernel() {
    int t = threadIdx.x;
    int lane = t & 31, w = t >> 5;
    int v = (t < SCAN_B) ? g_bsum[t] : 0;
    int incl = v;
#pragma unroll
    for (int o = 1; o < 32; o <<= 1) {
        int u = __shfl_up_sync(0xffffffffu, incl, o);
        if (lane >= o) incl += u;
    }
    __shared__ int ws[8], ws2[8];
    if (lane == 31) ws[w] = incl;
    __syncthreads();
    if (t < 8) {
        int wv = ws[t];
        int wi = wv;
#pragma unroll
        for (int o = 1; o < 8; o <<= 1) {
            int u = __shfl_up_sync(0xffu, wi, o);
            if (t >= o) wi += u;
        }
        ws2[t] = wi - wv;   // exclusive
    }
    __syncthreads();
    if (t < SCAN_B) g_bbase[t] = ws2[w] + incl - v;
}

__global__ void csr_offsets_kernel() {
    int b = blockIdx.x;
    int t = threadIdx.x;
    int i = b * 256 + t;
    int lane = t & 31, w = t >> 5;
    int v = (i < NNODES) ? g_deg[i] : 0;
    int incl = v;
#pragma unroll
    for (int o = 1; o < 32; o <<= 1) {
        int u = __shfl_up_sync(0xffffffffu, incl, o);
        if (lane >= o) incl += u;
    }
    __shared__ int ws[8], ws2[8];
    if (lane == 31) ws[w] = incl;
    __syncthreads();
    if (t < 8) {
        int wv = ws[t];
        int wi = wv;
#pragma unroll
        for (int o = 1; o < 8; o <<= 1) {
            int u = __shfl_up_sync(0xffu, wi, o);
            if (t >= o) wi += u;
        }
        ws2[t] = wi - wv;
    }
    __syncthreads();
    if (i < NNODES) {
        int off = g_bbase[b] + ws2[w] + incl - v;
        g_off[i] = off;
        g_pos[i] = off;
    }
}

__global__ void scatter_kernel(const void* __restrict__ ei) {
    int idx = blockIdx.x * blockDim.x + threadIdx.x;
    if (idx < NEDGES) {
        int s, d;
        load_edge(ei, idx, s, d);
        int p = atomicAdd(&g_pos[d], 1);
        g_esrc[p] = s;
    } else if (idx < TOTE) {
        int i = idx - NEDGES;           // self loop
        int p = atomicAdd(&g_pos[i], 1);
        g_esrc[p] = i;
    }
}

// ---------------- W1 pre-split to bf16 hi/lo, col-major ----------------
__global__ void convertB_kernel(const float* __restrict__ W1) {
    int o = blockIdx.x * 256 + threadIdx.x;     // o = n*512 + k
    if (o >= C_HID * C_IN) return;
    int n = o >> 9, k = o & 511;
    float v = W1[(size_t)k * C_HID + n];
    __nv_bfloat16 h = __float2bfloat16(v);
    g_Bth[o] = h;
    g_Btl[o] = __float2bfloat16(v - __bfloat162float(h));
}

// ---------------- tensor-core GEMM: g_h1 = x @ W1 (bf16 3-term split) -------
// Fused epilogue: also computes g_asrc1/g_adst1 = h1 . att_{src,dst}.
#define GK 32           // K chunk
#define AS 40           // A smem row stride (halves)
#define BTS 40          // Bt smem row stride (halves)

__device__ __forceinline__ void mma16816(float* c, const uint32_t* a,
                                         uint32_t b0, uint32_t b1) {
    asm volatile(
        "mma.sync.aligned.m16n8k16.row.col.f32.bf16.bf16.f32 "
        "{%0,%1,%2,%3},{%4,%5,%6,%7},{%8,%9},{%0,%1,%2,%3};"
        : "+f"(c[0]), "+f"(c[1]), "+f"(c[2]), "+f"(c[3])
        : "r"(a[0]), "r"(a[1]), "r"(a[2]), "r"(a[3]), "r"(b0), "r"(b1));
}

__global__ __launch_bounds__(256, 2) void gemm1_bf16_kernel(
    const float* __restrict__ A,        // x  [NNODES, 512]
    const float* __restrict__ att_src,  // [128]
    const float* __restrict__ att_dst)  // [128]
{
    __shared__ __align__(16) __nv_bfloat16 Ah[128][AS];
    __shared__ __align__(16) __nv_bfloat16 Al[128][AS];
    __shared__ __align__(16) __nv_bfloat16 Bth_s[128][BTS];
    __shared__ __align__(16) __nv_bfloat16 Btl_s[128][BTS];
    __shared__ float sAs[128], sAd[128];
    __shared__ float sPs[128][2], sPd[128][2];

    const int tid = threadIdx.x;
    const int lane = tid & 31;
    const int wid = tid >> 5;
    const int warp_m = wid & 3;
    const int warp_n = wid >> 2;
    const int g = lane >> 2;
    const int t4 = lane & 3;
    const int m0 = blockIdx.x * 128;

    if (tid < 128) {
        sAs[tid] = att_src[tid];
        sAd[tid] = att_dst[tid];
    }

    float acc[2][8][4];
#pragma unroll
    for (int mi = 0; mi < 2; mi++)
#pragma unroll
        for (int ni = 0; ni < 8; ni++)
#pragma unroll
            for (int q = 0; q < 4; q++) acc[mi][ni][q] = 0.f;

    float4 pa[4];
    uint4 pbh[2], pbl[2];

#pragma unroll
    for (int i = 0; i < 4; i++) {
        int flat = i * 256 + tid;
        int row = flat >> 3, c4 = (flat & 7) * 4;
        int gr = m0 + row;
        pa[i] = (gr < NNODES) ? *(const float4*)(A + (size_t)gr * C_IN + c4)
                              : make_float4(0.f, 0.f, 0.f, 0.f);
    }
#pragma unroll
    for (int i = 0; i < 2; i++) {
        int u = i * 256 + tid;
        int n = u >> 2, kq = u & 3;
        pbh[i] = *(const uint4*)(g_Bth + (size_t)n * C_IN + kq * 8);
        pbl[i] = *(const uint4*)(g_Btl + (size_t)n * C_IN + kq * 8);
    }

    for (int kc = 0; kc < C_IN / GK; kc++) {
#pragma unroll
        for (int i = 0; i < 4; i++) {
            int flat = i * 256 + tid;
            int row = flat >> 3, c4 = (flat & 7) * 4;
            float4 v = pa[i];
            __nv_bfloat162 h01 = __floats2bfloat162_rn(v.x, v.y);
            __nv_bfloat162 h23 = __floats2bfloat162_rn(v.z, v.w);
            float r0 = v.x - __bfloat162float(h01.x);
            float r1 = v.y - __bfloat162float(h01.y);
            float r2 = v.z - __bfloat162float(h23.x);
            float r3 = v.w - __bfloat162float(h23.y);
            *(__nv_bfloat162*)&Ah[row][c4]     = h01;
            *(__nv_bfloat162*)&Ah[row][c4 + 2] = h23;
            *(__nv_bfloat162*)&Al[row][c4]     = __floats2bfloat162_rn(r0, r1);
            *(__nv_bfloat162*)&Al[row][c4 + 2] = __floats2bfloat162_rn(r2, r3);
        }
#pragma unroll
        for (int i = 0; i < 2; i++) {
            int u = i * 256 + tid;
            int n = u >> 2, kq = u & 3;
            *(uint4*)&Bth_s[n][kq * 8] = pbh[i];
            *(uint4*)&Btl_s[n][kq * 8] = pbl[i];
        }
        __syncthreads();

        if (kc + 1 < C_IN / GK) {
            int k0n = (kc + 1) * GK;
#pragma unroll
            for (int i = 0; i < 4; i++) {
                int flat = i * 256 + tid;
                int row = flat >> 3, c4 = (flat & 7) * 4;
                int gr = m0 + row;
                pa[i] = (gr < NNODES)
                          ? *(const float4*)(A + (size_t)gr * C_IN + k0n + c4)
                          : make_float4(0.f, 0.f, 0.f, 0.f);
            }
#pragma unroll
            for (int i = 0; i < 2; i++) {
                int u = i * 256 + tid;
                int n = u >> 2, kq = u & 3;
                pbh[i] = *(const uint4*)(g_Bth + (size_t)n * C_IN + k0n + kq * 8);
                pbl[i] = *(const uint4*)(g_Btl + (size_t)n * C_IN + k0n + kq * 8);
            }
        }

#pragma unroll
        for (int s = 0; s < GK; s += 16) {
            uint32_t ah[2][4], al[2][4];
#pragma unroll
            for (int mi = 0; mi < 2; mi++) {
                int r = warp_m * 32 + mi * 16 + g;
                int c = s + t4 * 2;
                ah[mi][0] = *(const uint32_t*)&Ah[r][c];
                ah[mi][1] = *(const uint32_t*)&Ah[r + 8][c];
                ah[mi][2] = *(const uint32_t*)&Ah[r][c + 8];
                ah[mi][3] = *(const uint32_t*)&Ah[r + 8][c + 8];
                al[mi][0] = *(const uint32_t*)&Al[r][c];
                al[mi][1] = *(const uint32_t*)&Al[r + 8][c];
                al[mi][2] = *(const uint32_t*)&Al[r][c + 8];
                al[mi][3] = *(const uint32_t*)&Al[r + 8][c + 8];
            }
            int k0 = s + t4 * 2;
#pragma unroll
            for (int ni = 0; ni < 8; ni++) {
                int n = warp_n * 64 + ni * 8 + g;
                uint32_t bh0 = *(const uint32_t*)&Bth_s[n][k0];
                uint32_t bh1 = *(const uint32_t*)&Bth_s[n][k0 + 8];
                uint32_t bl0 = *(const uint32_t*)&Btl_s[n][k0];
                uint32_t bl1 = *(const uint32_t*)&Btl_s[n][k0 + 8];
#pragma unroll
                for (int mi = 0; mi < 2; mi++) {
                    mma16816(acc[mi][ni], ah[mi], bh0, bh1);   // hi*hi
                    mma16816(acc[mi][ni], ah[mi], bl0, bl1);   // hi*lo
                    mma16816(acc[mi][ni], al[mi], bh0, bh1);   // lo*hi
                }
            }
        }
        __syncthreads();
    }

    // ---- epilogue: store h1 + fused attention dot products ----
#pragma unroll
    for (int mi = 0; mi < 2; mi++) {
        float psA = 0.f, psB = 0.f, pdA = 0.f, pdB = 0.f;
#pragma unroll
        for (int ni = 0; ni < 8; ni++) {
            int r = m0 + warp_m * 32 + mi * 16 + g;
            int c = warp_n * 64 + ni * 8 + t4 * 2;
            if (r < NNODES)
                *(float2*)(g_h1 + (size_t)r * C_HID + c) =
                    make_float2(acc[mi][ni][0], acc[mi][ni][1]);
            if (r + 8 < NNODES)
                *(float2*)(g_h1 + (size_t)(r + 8) * C_HID + c) =
                    make_float2(acc[mi][ni][2], acc[mi][ni][3]);
            float a0 = sAs[c], a1 = sAs[c + 1];
            float d0 = sAd[c], d1 = sAd[c + 1];
            psA += acc[mi][ni][0] * a0 + acc[mi][ni][1] * a1;
            psB += acc[mi][ni][2] * a0 + acc[mi][ni][3] * a1;
            pdA += acc[mi][ni][0] * d0 + acc[mi][ni][1] * d1;
            pdB += acc[mi][ni][2] * d0 + acc[mi][ni][3] * d1;
        }
#pragma unroll
        for (int o = 1; o <= 2; o <<= 1) {
            psA += __shfl_xor_sync(0xffffffffu, psA, o);
            psB += __shfl_xor_sync(0xffffffffu, psB, o);
            pdA += __shfl_xor_sync(0xffffffffu, pdA, o);
            pdB += __shfl_xor_sync(0xffffffffu, pdB, o);
        }
        if (t4 == 0) {
            int rl = warp_m * 32 + mi * 16 + g;
            sPs[rl][warp_n] = psA;  sPs[rl + 8][warp_n] = psB;
            sPd[rl][warp_n] = pdA;  sPd[rl + 8][warp_n] = pdB;
        }
    }
    __syncthreads();
    if (tid < 128) {
        int r = m0 + tid;
        if (r < NNODES) {
            g_asrc1[r] = sPs[tid][0] + sPs[tid][1];
            g_adst1[r] = sPd[tid][0] + sPd[tid][1];
        }
    }
}

// ---------------- layer-1 aggregation + FUSED layer-2 projection -----------
// Warp per dst node. Lane l owns channels 4l..4l+3. No max-shift softmax.
__global__ __launch_bounds__(256) void agg1_kernel(const float* __restrict__ bias1,
                                                   const float* __restrict__ W2,
                                                   const float* __restrict__ as2,
                                                   const float* __restrict__ ad2) {
    __shared__ float exw[8][W_CAP];
    __shared__ float sW2[C_HID * 6];
    __shared__ float sa2[6], sd2[6];

    int tid = threadIdx.x;
    for (int i = tid; i < C_HID * 6; i += 256) sW2[i] = W2[i];
    if (tid < 6) { sa2[tid] = as2[tid]; sd2[tid] = ad2[tid]; }
    __syncthreads();

    int warp = tid >> 5;
    int lane = tid & 31;
    int d = blockIdx.x * 8 + warp;
    if (d >= NNODES) return;

    int start = g_off[d];
    int cnt = g_deg[d];
    float adst = g_adst1[d];

    // pass 1: denominators, cache exp in smem
    float sum = 0.f;
    for (int j = lane; j < cnt; j += 32) {
        int s = g_esrc[start + j];
        float e = g_asrc1[s] + adst;
        e = e >= 0.f ? e : NEG_SLOPE * e;
        float ex = __expf(e);
        if (j < W_CAP) exw[warp][j] = ex;
        sum += ex;
    }
    __syncwarp();
#pragma unroll
    for (int o = 16; o > 0; o >>= 1) sum += __shfl_xor_sync(0xffffffffu, sum, o);
    float inv = 1.f / (sum + 1e-16f);

    // pass 2: weighted row gather, 2-way unrolled for MLP
    float4 acc = make_float4(0.f, 0.f, 0.f, 0.f);
    float4 accB = make_float4(0.f, 0.f, 0.f, 0.f);
    int j = 0;
    for (; j + 1 < cnt; j += 2) {
        int s0 = g_esrc[start + j];
        int s1 = g_esrc[start + j + 1];
        float ex0, ex1;
        if (j < W_CAP) ex0 = exw[warp][j];
        else {
            float e = g_asrc1[s0] + adst;
            e = e >= 0.f ? e : NEG_SLOPE * e;
            ex0 = __expf(e);
        }
        if (j + 1 < W_CAP) ex1 = exw[warp][j + 1];
        else {
            float e = g_asrc1[s1] + adst;
            e = e >= 0.f ? e : NEG_SLOPE * e;
            ex1 = __expf(e);
        }
        float4 h0 = *(const float4*)(g_h1 + (size_t)s0 * 128 + lane * 4);
        float4 h1 = *(const float4*)(g_h1 + (size_t)s1 * 128 + lane * 4);
        acc.x += h0.x * ex0;  acc.y += h0.y * ex0;
        acc.z += h0.z * ex0;  acc.w += h0.w * ex0;
        accB.x += h1.x * ex1; accB.y += h1.y * ex1;
        accB.z += h1.z * ex1; accB.w += h1.w * ex1;
    }
    if (j < cnt) {
        int s0 = g_esrc[start + j];
        float ex0;
        if (j < W_CAP) ex0 = exw[warp][j];
        else {
            float e = g_asrc1[s0] + adst;
            e = e >= 0.f ? e : NEG_SLOPE * e;
            ex0 = __expf(e);
        }
        float4 h0 = *(const float4*)(g_h1 + (size_t)s0 * 128 + lane * 4);
        acc.x += h0.x * ex0; acc.y += h0.y * ex0;
        acc.z += h0.z * ex0; acc.w += h0.w * ex0;
    }
    acc.x += accB.x; acc.y += accB.y; acc.z += accB.z; acc.w += accB.w;

    float4 b4 = *(const float4*)(bias1 + lane * 4);
    float vx = acc.x * inv + b4.x; vx = vx > 0.f ? vx : 0.f;
    float vy = acc.y * inv + b4.y; vy = vy > 0.f ? vy : 0.f;
    float vz = acc.z * inv + b4.z; vz = vz > 0.f ? vz : 0.f;
    float vw = acc.w * inv + b4.w; vw = vw > 0.f ? vw : 0.f;

    // fused layer-2 projection: p[6] = v(128) @ W2(128x6)
    float p[6];
    {
        int c = lane * 4;
        const float* w0 = &sW2[(c + 0) * 6];
        const float* w1 = &sW2[(c + 1) * 6];
        const float* w2r = &sW2[(c + 2) * 6];
        const float* w3 = &sW2[(c + 3) * 6];
#pragma unroll
        for (int jj = 0; jj < 6; jj++)
            p[jj] = vx * w0[jj] + vy * w1[jj] + vz * w2r[jj] + vw * w3[jj];
    }
#pragma unroll
    for (int o = 16; o > 0; o >>= 1)
#pragma unroll
        for (int jj = 0; jj < 6; jj++) p[jj] += __shfl_xor_sync(0xffffffffu, p[jj], o);

    if (lane == 0) {
        float* hp = g_h2 + (size_t)d * 6;
#pragma unroll
        for (int jj = 0; jj < 6; jj++) hp[jj] = p[jj];
        g_asrc2[d * 3 + 0] = p[0] * sa2[0] + p[1] * sa2[1];
        g_asrc2[d * 3 + 1] = p[2] * sa2[2] + p[3] * sa2[3];
        g_asrc2[d * 3 + 2] = p[4] * sa2[4] + p[5] * sa2[5];
        g_adst2[d * 3 + 0] = p[0] * sd2[0] + p[1] * sd2[1];
        g_adst2[d * 3 + 1] = p[2] * sd2[2] + p[3] * sd2[3];
        g_adst2[d * 3 + 2] = p[4] * sd2[4] + p[5] * sd2[5];
    }
}

// ---------------- layer-2 aggregation + head mean (warp per dst node) ------
__global__ __launch_bounds__(256) void agg2_kernel(const float* __restrict__ bias2,
                                                   float* __restrict__ out) {
    __shared__ float ca0[8][W_CAP], ca1[8][W_CAP], ca2[8][W_CAP];
    int warp = threadIdx.x >> 5;
    int lane = threadIdx.x & 31;
    int d = blockIdx.x * 8 + warp;
    if (d >= NNODES) return;

    int start = g_off[d];
    int cnt = g_deg[d];

    float ad0 = g_adst2[d * 3 + 0];
    float ad1 = g_adst2[d * 3 + 1];
    float ad2v = g_adst2[d * 3 + 2];

    // pass 1: denominators + cache exps
    float s0 = 0.f, s1 = 0.f, s2 = 0.f;
    for (int j = lane; j < cnt; j += 32) {
        int s = g_esrc[start + j];
        float e0 = g_asrc2[s * 3 + 0] + ad0; e0 = e0 >= 0.f ? e0 : NEG_SLOPE * e0;
        float e1 = g_asrc2[s * 3 + 1] + ad1; e1 = e1 >= 0.f ? e1 : NEG_SLOPE * e1;
        float e2 = g_asrc2[s * 3 + 2] + ad2v; e2 = e2 >= 0.f ? e2 : NEG_SLOPE * e2;
        float a0 = __expf(e0), a1 = __expf(e1), a2 = __expf(e2);
        if (j < W_CAP) { ca0[warp][j] = a0; ca1[warp][j] = a1; ca2[warp][j] = a2; }
        s0 += a0; s1 += a1; s2 += a2;
    }
    __syncwarp();
#pragma unroll
    for (int o = 16; o > 0; o >>= 1) {
        s0 += __shfl_xor_sync(0xffffffffu, s0, o);
        s1 += __shfl_xor_sync(0xffffffffu, s1, o);
        s2 += __shfl_xor_sync(0xffffffffu, s2, o);
    }
    float i0 = 1.f / (s0 + 1e-16f);
    float i1 = 1.f / (s1 + 1e-16f);
    float i2 = 1.f / (s2 + 1e-16f);

    // pass 2: weighted accumulation using cached exps
    float acc[6] = {0.f, 0.f, 0.f, 0.f, 0.f, 0.f};
    for (int j = lane; j < cnt; j += 32) {
        int s = g_esrc[start + j];
        float a0, a1, a2;
        if (j < W_CAP) { a0 = ca0[warp][j]; a1 = ca1[warp][j]; a2 = ca2[warp][j]; }
        else {
            float e0 = g_asrc2[s * 3 + 0] + ad0; e0 = e0 >= 0.f ? e0 : NEG_SLOPE * e0;
            float e1 = g_asrc2[s * 3 + 1] + ad1; e1 = e1 >= 0.f ? e1 : NEG_SLOPE * e1;
            float e2 = g_asrc2[s * 3 + 2] + ad2v; e2 = e2 >= 0.f ? e2 : NEG_SLOPE * e2;
            a0 = __expf(e0); a1 = __expf(e1); a2 = __expf(e2);
        }
        const float* hp = g_h2 + (size_t)s * 6;
        acc[0] += hp[0] * a0; acc[1] += hp[1] * a0;
        acc[2] += hp[2] * a1; acc[3] += hp[3] * a1;
        acc[4] += hp[4] * a2; acc[5] += hp[5] * a2;
    }
#pragma unroll
    for (int o = 16; o > 0; o >>= 1)
#pragma unroll
        for (int j = 0; j < 6; j++) acc[j] += __shfl_xor_sync(0xffffffffu, acc[j], o);

    if (lane == 0) {
        out[d * 2 + 0] = (acc[0] * i0 + acc[2] * i1 + acc[4] * i2) * (1.f / 3.f) + bias2[0];
        out[d * 2 + 1] = (acc[1] * i0 + acc[3] * i1 + acc[5] * i2) * (1.f / 3.f) + bias2[1];
    }
}

// ---------------- launch ----------------
extern "C" void kernel_launch(void* const* d_in, const int* in_sizes, int n_in,
                              void* d_out, int out_size) {
    const float* x   = (const float*)d_in[0];
    const void*  ei  = d_in[1];
    const float* W1  = (const float*)d_in[2];
    const float* as1 = (const float*)d_in[3];
    const float* ad1 = (const float*)d_in[4];
    const float* b1  = (const float*)d_in[5];
    const float* W2  = (const float*)d_in[6];
    const float* as2 = (const float*)d_in[7];
    const float* ad2 = (const float*)d_in[8];
    const float* b2  = (const float*)d_in[9];
    float* out = (float*)d_out;

    // one-time stream/event setup (host-side only; no device allocations)
    static cudaStream_t s2 = nullptr;
    static cudaEvent_t evFork = nullptr, evJoin = nullptr;
    if (s2 == nullptr) {
        cudaStreamCreateWithFlags(&s2, cudaStreamNonBlocking);
        cudaEventCreateWithFlags(&evFork, cudaEventDisableTiming);
        cudaEventCreateWithFlags(&evJoin, cudaEventDisableTiming);
    }

    // fork: GEMM chain on s2 (independent of CSR build)
    cudaEventRecord(evFork, 0);
    cudaStreamWaitEvent(s2, evFork, 0);
    convertB_kernel<<<(C_HID * C_IN + 255) / 256, 256, 0, s2>>>(W1);
    gemm1_bf16_kernel<<<(NNODES + 127) / 128, 256, 0, s2>>>(x, as1, ad1);
    cudaEventRecord(evJoin, s2);

    // CSR build on the origin stream (overlaps with GEMM)
    detect_kernel<<<1, 1>>>((const unsigned*)ei);
    init_deg_kernel<<<(NNODES + 255) / 256, 256>>>();
    count_kernel<<<(NEDGES + 255) / 256, 256>>>(ei);
    csr_partial_kernel<<<SCAN_B, 256>>>();
    csr_scanbase_kernel<<<1, 256>>>();
    csr_offsets_kernel<<<SCAN_B, 256>>>();
    scatter_kernel<<<(TOTE + 255) / 256, 256>>>(ei);

    // join: aggregation needs both CSR and GEMM results
    cudaStreamWaitEvent(0, evJoin, 0);
    agg1_kernel<<<(NNODES + 7) / 8, 256>>>(b1, W2, as2, ad2);
    agg2_kernel<<<(NNODES + 7) / 8, 256>>>(b2, out);
}

// round 16
// speedup vs baseline: 2.9047x; 1.0354x over previous
#include <cuda_runtime.h>
#include <cuda_bf16.h>
#include <cuda_fp16.h>
#include <cstdint>

#define NNODES 50000
#define NEDGES 800000
#define C_IN   512
#define C_HID  128
#define TOTE   (NEDGES + NNODES)   // edges + self loops
#define NEG_SLOPE 0.2f
#define SCAN_B ((NNODES + 255) / 256)   // 196
#define W_CAP 96                        // per-warp exp cache (max degree ~60)

// ---------------- scratch (static __device__, no allocations) ----------------
__device__ __half g_h1h[(size_t)NNODES * C_HID];   // x @ W1, fp16 (gather payload)
__device__ float g_asrc1[NNODES];
__device__ float g_adst1[NNODES];
__device__ float g_h2[(size_t)NNODES * 6];         // layer2 features [N,3,2]
__device__ float g_asrc2[(size_t)NNODES * 3];
__device__ float g_adst2[(size_t)NNODES * 3];
__device__ int   g_deg[NNODES];
__device__ int   g_off[NNODES];
__device__ int   g_pos[NNODES];
__device__ int   g_esrc[TOTE];                     // src node per edge, grouped by dst
__device__ int   g_is64;                           // edge_index dtype flag
__device__ int   g_bsum[SCAN_B];
__device__ int   g_bbase[SCAN_B];
// W1 pre-split into bf16 hi/lo planes, col-major [n][k]
__device__ __align__(16) __nv_bfloat16 g_Bth[(size_t)C_HID * C_IN];
__device__ __align__(16) __nv_bfloat16 g_Btl[(size_t)C_HID * C_IN];

// ---------------- dtype detection for edge_index ----------------
__global__ void detect_kernel(const unsigned* __restrict__ ei_words) {
    int flag = 1;
    for (int i = 0; i < 64; i++)
        if (ei_words[2 * i + 1] != 0u) { flag = 0; break; }
    g_is64 = flag;
}

__device__ __forceinline__ void load_edge(const void* ei, int e, int& s, int& d) {
    if (g_is64) {
        const long long* p = (const long long*)ei;
        s = (int)p[e];
        d = (int)p[NEDGES + e];
    } else {
        const int* p = (const int*)ei;
        s = p[e];
        d = p[NEDGES + e];
    }
}

// ---------------- CSR build ----------------
__global__ void init_deg_kernel() {
    int i = blockIdx.x * blockDim.x + threadIdx.x;
    if (i < NNODES) g_deg[i] = 1;   // self loop
}

__global__ void count_kernel(const void* __restrict__ ei) {
    int e = blockIdx.x * blockDim.x + threadIdx.x;
    if (e >= NEDGES) return;
    int s, d;
    load_edge(ei, e, s, d);
    atomicAdd(&g_deg[d], 1);
}

__global__ void csr_partial_kernel() {
    int i = blockIdx.x * 256 + threadIdx.x;
    int v = (i < NNODES) ? g_deg[i] : 0;
#pragma unroll
    for (int o = 16; o > 0; o >>= 1) v += __shfl_xor_sync(0xffffffffu, v, o);
    __shared__ int ws[8];
    if ((threadIdx.x & 31) == 0) ws[threadIdx.x >> 5] = v;
    __syncthreads();
    if (threadIdx.x == 0) {
        int s = 0;
#pragma unroll
        for (int w = 0; w < 8; w++) s += ws[w];
        g_bsum[blockIdx.x] = s;
    }
}

__global__ void csr_scanbase_kernel() {
    int t = threadIdx.x;
    int lane = t & 31, w = t >> 5;
    int v = (t < SCAN_B) ? g_bsum[t] : 0;
    int incl = v;
#pragma unroll
    for (int o = 1; o < 32; o <<= 1) {
        int u = __shfl_up_sync(0xffffffffu, incl, o);
        if (lane >= o) incl += u;
    }
    __shared__ int ws[8], ws2[8];
    if (lane == 31) ws[w] = incl;
    __syncthreads();
    if (t < 8) {
        int wv = ws[t];
        int wi = wv;
#pragma unroll
        for (int o = 1; o < 8; o <<= 1) {
            int u = __shfl_up_sync(0xffu, wi, o);
            if (t >= o) wi += u;
        }
        ws2[t] = wi - wv;   // exclusive
    }
    __syncthreads();
    if (t < SCAN_B) g_bbase[t] = ws2[w] + incl - v;
}

__global__ void csr_offsets_kernel() {
    int b = blockIdx.x;
    int t = threadIdx.x;
    int i = b * 256 + t;
    int lane = t & 31, w = t >> 5;
    int v = (i < NNODES) ? g_deg[i] : 0;
    int incl = v;
#pragma unroll
    for (int o = 1; o < 32; o <<= 1) {
        int u = __shfl_up_sync(0xffffffffu, incl, o);
        if (lane >= o) incl += u;
    }
    __shared__ int ws[8], ws2[8];
    if (lane == 31) ws[w] = incl;
    __syncthreads();
    if (t < 8) {
        int wv = ws[t];
        int wi = wv;
#pragma unroll
        for (int o = 1; o < 8; o <<= 1) {
            int u = __shfl_up_sync(0xffu, wi, o);
            if (t >= o) wi += u;
        }
        ws2[t] = wi - wv;
    }
    __syncthreads();
    if (i < NNODES) {
        int off = g_bbase[b] + ws2[w] + incl - v;
        g_off[i] = off;
        g_pos[i] = off;
    }
}

__global__ void scatter_kernel(const void* __restrict__ ei) {
    int idx = blockIdx.x * blockDim.x + threadIdx.x;
    if (idx < NEDGES) {
        int s, d;
        load_edge(ei, idx, s, d);
        int p = atomicAdd(&g_pos[d], 1);
        g_esrc[p] = s;
    } else if (idx < TOTE) {
        int i = idx - NEDGES;           // self loop
        int p = atomicAdd(&g_pos[i], 1);
        g_esrc[p] = i;
    }
}

// ---------------- W1 pre-split to bf16 hi/lo, col-major ----------------
__global__ void convertB_kernel(const float* __restrict__ W1) {
    int o = blockIdx.x * 256 + threadIdx.x;     // o = n*512 + k
    if (o >= C_HID * C_IN) return;
    int n = o >> 9, k = o & 511;
    float v = W1[(size_t)k * C_HID + n];
    __nv_bfloat16 h = __float2bfloat16(v);
    g_Bth[o] = h;
    g_Btl[o] = __float2bfloat16(v - __bfloat162float(h));
}

// ---------------- tensor-core GEMM: g_h1h = x @ W1 (bf16 3-term split) ------
// Fused epilogue: fp16 h1 store + fp32 attention dot products.
#define GK 32           // K chunk
#define AS 40           // A smem row stride (halves)
#define BTS 40          // Bt smem row stride (halves)

__device__ __forceinline__ void mma16816(float* c, const uint32_t* a,
                                         uint32_t b0, uint32_t b1) {
    asm volatile(
        "mma.sync.aligned.m16n8k16.row.col.f32.bf16.bf16.f32 "
        "{%0,%1,%2,%3},{%4,%5,%6,%7},{%8,%9},{%0,%1,%2,%3};"
        : "+f"(c[0]), "+f"(c[1]), "+f"(c[2]), "+f"(c[3])
        : "r"(a[0]), "r"(a[1]), "r"(a[2]), "r"(a[3]), "r"(b0), "r"(b1));
}

__global__ __launch_bounds__(256, 2) void gemm1_bf16_kernel(
    const float* __restrict__ A,        // x  [NNODES, 512]
    const float* __restrict__ att_src,  // [128]
    const float* __restrict__ att_dst)  // [128]
{
    __shared__ __align__(16) __nv_bfloat16 Ah[128][AS];
    __shared__ __align__(16) __nv_bfloat16 Al[128][AS];
    __shared__ __align__(16) __nv_bfloat16 Bth_s[128][BTS];
    __shared__ __align__(16) __nv_bfloat16 Btl_s[128][BTS];
    __shared__ float sAs[128], sAd[128];
    __shared__ float sPs[128][2], sPd[128][2];

    const int tid = threadIdx.x;
    const int lane = tid & 31;
    const int wid = tid >> 5;
    const int warp_m = wid & 3;
    const int warp_n = wid >> 2;
    const int g = lane >> 2;
    const int t4 = lane & 3;
    const int m0 = blockIdx.x * 128;

    if (tid < 128) {
        sAs[tid] = att_src[tid];
        sAd[tid] = att_dst[tid];
    }

    float acc[2][8][4];
#pragma unroll
    for (int mi = 0; mi < 2; mi++)
#pragma unroll
        for (int ni = 0; ni < 8; ni++)
#pragma unroll
            for (int q = 0; q < 4; q++) acc[mi][ni][q] = 0.f;

    float4 pa[4];
    uint4 pbh[2], pbl[2];

#pragma unroll
    for (int i = 0; i < 4; i++) {
        int flat = i * 256 + tid;
        int row = flat >> 3, c4 = (flat & 7) * 4;
        int gr = m0 + row;
        pa[i] = (gr < NNODES) ? *(const float4*)(A + (size_t)gr * C_IN + c4)
                              : make_float4(0.f, 0.f, 0.f, 0.f);
    }
#pragma unroll
    for (int i = 0; i < 2; i++) {
        int u = i * 256 + tid;
        int n = u >> 2, kq = u & 3;
        pbh[i] = *(const uint4*)(g_Bth + (size_t)n * C_IN + kq * 8);
        pbl[i] = *(const uint4*)(g_Btl + (size_t)n * C_IN + kq * 8);
    }

    for (int kc = 0; kc < C_IN / GK; kc++) {
#pragma unroll
        for (int i = 0; i < 4; i++) {
            int flat = i * 256 + tid;
            int row = flat >> 3, c4 = (flat & 7) * 4;
            float4 v = pa[i];
            __nv_bfloat162 h01 = __floats2bfloat162_rn(v.x, v.y);
            __nv_bfloat162 h23 = __floats2bfloat162_rn(v.z, v.w);
            float r0 = v.x - __bfloat162float(h01.x);
            float r1 = v.y - __bfloat162float(h01.y);
            float r2 = v.z - __bfloat162float(h23.x);
            float r3 = v.w - __bfloat162float(h23.y);
            *(__nv_bfloat162*)&Ah[row][c4]     = h01;
            *(__nv_bfloat162*)&Ah[row][c4 + 2] = h23;
            *(__nv_bfloat162*)&Al[row][c4]     = __floats2bfloat162_rn(r0, r1);
            *(__nv_bfloat162*)&Al[row][c4 + 2] = __floats2bfloat162_rn(r2, r3);
        }
#pragma unroll
        for (int i = 0; i < 2; i++) {
            int u = i * 256 + tid;
            int n = u >> 2, kq = u & 3;
            *(uint4*)&Bth_s[n][kq * 8] = pbh[i];
            *(uint4*)&Btl_s[n][kq * 8] = pbl[i];
        }
        __syncthreads();

        if (kc + 1 < C_IN / GK) {
            int k0n = (kc + 1) * GK;
#pragma unroll
            for (int i = 0; i < 4; i++) {
                int flat = i * 256 + tid;
                int row = flat >> 3, c4 = (flat & 7) * 4;
                int gr = m0 + row;
                pa[i] = (gr < NNODES)
                          ? *(const float4*)(A + (size_t)gr * C_IN + k0n + c4)
                          : make_float4(0.f, 0.f, 0.f, 0.f);
            }
#pragma unroll
            for (int i = 0; i < 2; i++) {
                int u = i * 256 + tid;
                int n = u >> 2, kq = u & 3;
                pbh[i] = *(const uint4*)(g_Bth + (size_t)n * C_IN + k0n + kq * 8);
                pbl[i] = *(const uint4*)(g_Btl + (size_t)n * C_IN + k0n + kq * 8);
            }
        }

#pragma unroll
        for (int s = 0; s < GK; s += 16) {
            uint32_t ah[2][4], al[2][4];
#pragma unroll
            for (int mi = 0; mi < 2; mi++) {
                int r = warp_m * 32 + mi * 16 + g;
                int c = s + t4 * 2;
                ah[mi][0] = *(const uint32_t*)&Ah[r][c];
                ah[mi][1] = *(const uint32_t*)&Ah[r + 8][c];
                ah[mi][2] = *(const uint32_t*)&Ah[r][c + 8];
                ah[mi][3] = *(const uint32_t*)&Ah[r + 8][c + 8];
                al[mi][0] = *(const uint32_t*)&Al[r][c];
                al[mi][1] = *(const uint32_t*)&Al[r + 8][c];
                al[mi][2] = *(const uint32_t*)&Al[r][c + 8];
                al[mi][3] = *(const uint32_t*)&Al[r + 8][c + 8];
            }
            int k0 = s + t4 * 2;
#pragma unroll
            for (int ni = 0; ni < 8; ni++) {
                int n = warp_n * 64 + ni * 8 + g;
                uint32_t bh0 = *(const uint32_t*)&Bth_s[n][k0];
                uint32_t bh1 = *(const uint32_t*)&Bth_s[n][k0 + 8];
                uint32_t bl0 = *(const uint32_t*)&Btl_s[n][k0];
                uint32_t bl1 = *(const uint32_t*)&Btl_s[n][k0 + 8];
#pragma unroll
                for (int mi = 0; mi < 2; mi++) {
                    mma16816(acc[mi][ni], ah[mi], bh0, bh1);   // hi*hi
                    mma16816(acc[mi][ni], ah[mi], bl0, bl1);   // hi*lo
                    mma16816(acc[mi][ni], al[mi], bh0, bh1);   // lo*hi
                }
            }
        }
        __syncthreads();
    }

    // ---- epilogue: store fp16 h1 + fused fp32 attention dot products ----
#pragma unroll
    for (int mi = 0; mi < 2; mi++) {
        float psA = 0.f, psB = 0.f, pdA = 0.f, pdB = 0.f;
#pragma unroll
        for (int ni = 0; ni < 8; ni++) {
            int r = m0 + warp_m * 32 + mi * 16 + g;
            int c = warp_n * 64 + ni * 8 + t4 * 2;
            if (r < NNODES)
                *(__half2*)(g_h1h + (size_t)r * C_HID + c) =
                    __floats2half2_rn(acc[mi][ni][0], acc[mi][ni][1]);
            if (r + 8 < NNODES)
                *(__half2*)(g_h1h + (size_t)(r + 8) * C_HID + c) =
                    __floats2half2_rn(acc[mi][ni][2], acc[mi][ni][3]);
            float a0 = sAs[c], a1 = sAs[c + 1];
            float d0 = sAd[c], d1 = sAd[c + 1];
            psA += acc[mi][ni][0] * a0 + acc[mi][ni][1] * a1;
            psB += acc[mi][ni][2] * a0 + acc[mi][ni][3] * a1;
            pdA += acc[mi][ni][0] * d0 + acc[mi][ni][1] * d1;
            pdB += acc[mi][ni][2] * d0 + acc[mi][ni][3] * d1;
        }
#pragma unroll
        for (int o = 1; o <= 2; o <<= 1) {
            psA += __shfl_xor_sync(0xffffffffu, psA, o);
            psB += __shfl_xor_sync(0xffffffffu, psB, o);
            pdA += __shfl_xor_sync(0xffffffffu, pdA, o);
            pdB += __shfl_xor_sync(0xffffffffu, pdB, o);
        }
        if (t4 == 0) {
            int rl = warp_m * 32 + mi * 16 + g;
            sPs[rl][warp_n] = psA;  sPs[rl + 8][warp_n] = psB;
            sPd[rl][warp_n] = pdA;  sPd[rl + 8][warp_n] = pdB;
        }
    }
    __syncthreads();
    if (tid < 128) {
        int r = m0 + tid;
        if (r < NNODES) {
            g_asrc1[r] = sPs[tid][0] + sPs[tid][1];
            g_adst1[r] = sPd[tid][0] + sPd[tid][1];
        }
    }
}

// ---------------- layer-1 aggregation + FUSED layer-2 projection -----------
// Warp per dst node. Lane l owns channels 4l..4l+3 (fp16 gather, fp32 math).
__global__ __launch_bounds__(256) void agg1_kernel(const float* __restrict__ bias1,
                                                   const float* __restrict__ W2,
                                                   const float* __restrict__ as2,
                                                   const float* __restrict__ ad2) {
    __shared__ float exw[8][W_CAP];
    __shared__ float sW2[C_HID * 6];
    __shared__ float sa2[6], sd2[6];

    int tid = threadIdx.x;
    for (int i = tid; i < C_HID * 6; i += 256) sW2[i] = W2[i];
    if (tid < 6) { sa2[tid] = as2[tid]; sd2[tid] = ad2[tid]; }
    __syncthreads();

    int warp = tid >> 5;
    int lane = tid & 31;
    int d = blockIdx.x * 8 + warp;
    if (d >= NNODES) return;

    int start = g_off[d];
    int cnt = g_deg[d];
    float adst = g_adst1[d];

    // pass 1: denominators, cache exp in smem
    float sum = 0.f;
    for (int j = lane; j < cnt; j += 32) {
        int s = g_esrc[start + j];
        float e = g_asrc1[s] + adst;
        e = e >= 0.f ? e : NEG_SLOPE * e;
        float ex = __expf(e);
        if (j < W_CAP) exw[warp][j] = ex;
        sum += ex;
    }
    __syncwarp();
#pragma unroll
    for (int o = 16; o > 0; o >>= 1) sum += __shfl_xor_sync(0xffffffffu, sum, o);
    float inv = 1.f / (sum + 1e-16f);

    // pass 2: weighted fp16-row gather, 2-way unrolled for MLP
    float4 acc = make_float4(0.f, 0.f, 0.f, 0.f);
    float4 accB = make_float4(0.f, 0.f, 0.f, 0.f);
    int j = 0;
    for (; j + 1 < cnt; j += 2) {
        int s0 = g_esrc[start + j];
        int s1 = g_esrc[start + j + 1];
        float ex0, ex1;
        if (j < W_CAP) ex0 = exw[warp][j];
        else {
            float e = g_asrc1[s0] + adst;
            e = e >= 0.f ? e : NEG_SLOPE * e;
            ex0 = __expf(e);
        }
        if (j + 1 < W_CAP) ex1 = exw[warp][j + 1];
        else {
            float e = g_asrc1[s1] + adst;
            e = e >= 0.f ? e : NEG_SLOPE * e;
            ex1 = __expf(e);
        }
        uint2 r0 = *(const uint2*)(g_h1h + (size_t)s0 * C_HID + lane * 4);
        uint2 r1 = *(const uint2*)(g_h1h + (size_t)s1 * C_HID + lane * 4);
        float2 a01 = __half22float2(*(const __half2*)&r0.x);
        float2 a23 = __half22float2(*(const __half2*)&r0.y);
        float2 b01 = __half22float2(*(const __half2*)&r1.x);
        float2 b23 = __half22float2(*(const __half2*)&r1.y);
        acc.x += a01.x * ex0;  acc.y += a01.y * ex0;
        acc.z += a23.x * ex0;  acc.w += a23.y * ex0;
        accB.x += b01.x * ex1; accB.y += b01.y * ex1;
        accB.z += b23.x * ex1; accB.w += b23.y * ex1;
    }
    if (j < cnt) {
        int s0 = g_esrc[start + j];
        float ex0;
        if (j < W_CAP) ex0 = exw[warp][j];
        else {
            float e = g_asrc1[s0] + adst;
            e = e >= 0.f ? e : NEG_SLOPE * e;
            ex0 = __expf(e);
        }
        uint2 r0 = *(const uint2*)(g_h1h + (size_t)s0 * C_HID + lane * 4);
        float2 a01 = __half22float2(*(const __half2*)&r0.x);
        float2 a23 = __half22float2(*(const __half2*)&r0.y);
        acc.x += a01.x * ex0; acc.y += a01.y * ex0;
        acc.z += a23.x * ex0; acc.w += a23.y * ex0;
    }
    acc.x += accB.x; acc.y += accB.y; acc.z += accB.z; acc.w += accB.w;

    float4 b4 = *(const float4*)(bias1 + lane * 4);
    float vx = acc.x * inv + b4.x; vx = vx > 0.f ? vx : 0.f;
    float vy = acc.y * inv + b4.y; vy = vy > 0.f ? vy : 0.f;
    float vz = acc.z * inv + b4.z; vz = vz > 0.f ? vz : 0.f;
    float vw = acc.w * inv + b4.w; vw = vw > 0.f ? vw : 0.f;

    // fused layer-2 projection: p[6] = v(128) @ W2(128x6)
    float p[6];
    {
        int c = lane * 4;
        const float* w0 = &sW2[(c + 0) * 6];
        const float* w1 = &sW2[(c + 1) * 6];
        const float* w2r = &sW2[(c + 2) * 6];
        const float* w3 = &sW2[(c + 3) * 6];
#pragma unroll
        for (int jj = 0; jj < 6; jj++)
            p[jj] = vx * w0[jj] + vy * w1[jj] + vz * w2r[jj] + vw * w3[jj];
    }
#pragma unroll
    for (int o = 16; o > 0; o >>= 1)
#pragma unroll
        for (int jj = 0; jj < 6; jj++) p[jj] += __shfl_xor_sync(0xffffffffu, p[jj], o);

    if (lane == 0) {
        float* hp = g_h2 + (size_t)d * 6;
#pragma unroll
        for (int jj = 0; jj < 6; jj++) hp[jj] = p[jj];
        g_asrc2[d * 3 + 0] = p[0] * sa2[0] + p[1] * sa2[1];
        g_asrc2[d * 3 + 1] = p[2] * sa2[2] + p[3] * sa2[3];
        g_asrc2[d * 3 + 2] = p[4] * sa2[4] + p[5] * sa2[5];
        g_adst2[d * 3 + 0] = p[0] * sd2[0] + p[1] * sd2[1];
        g_adst2[d * 3 + 1] = p[2] * sd2[2] + p[3] * sd2[3];
        g_adst2[d * 3 + 2] = p[4] * sd2[4] + p[5] * sd2[5];
    }
}

// ---------------- layer-2 aggregation + head mean (warp per dst node) ------
__global__ __launch_bounds__(256) void agg2_kernel(const float* __restrict__ bias2,
                                                   float* __restrict__ out) {
    __shared__ float ca0[8][W_CAP], ca1[8][W_CAP], ca2[8][W_CAP];
    int warp = threadIdx.x >> 5;
    int lane = threadIdx.x & 31;
    int d = blockIdx.x * 8 + warp;
    if (d >= NNODES) return;

    int start = g_off[d];
    int cnt = g_deg[d];

    float ad0 = g_adst2[d * 3 + 0];
    float ad1 = g_adst2[d * 3 + 1];
    float ad2v = g_adst2[d * 3 + 2];

    // pass 1: denominators + cache exps
    float s0 = 0.f, s1 = 0.f, s2 = 0.f;
    for (int j = lane; j < cnt; j += 32) {
        int s = g_esrc[start + j];
        float e0 = g_asrc2[s * 3 + 0] + ad0; e0 = e0 >= 0.f ? e0 : NEG_SLOPE * e0;
        float e1 = g_asrc2[s * 3 + 1] + ad1; e1 = e1 >= 0.f ? e1 : NEG_SLOPE * e1;
        float e2 = g_asrc2[s * 3 + 2] + ad2v; e2 = e2 >= 0.f ? e2 : NEG_SLOPE * e2;
        float a0 = __expf(e0), a1 = __expf(e1), a2 = __expf(e2);
        if (j < W_CAP) { ca0[warp][j] = a0; ca1[warp][j] = a1; ca2[warp][j] = a2; }
        s0 += a0; s1 += a1; s2 += a2;
    }
    __syncwarp();
#pragma unroll
    for (int o = 16; o > 0; o >>= 1) {
        s0 += __shfl_xor_sync(0xffffffffu, s0, o);
        s1 += __shfl_xor_sync(0xffffffffu, s1, o);
        s2 += __shfl_xor_sync(0xffffffffu, s2, o);
    }
    float i0 = 1.f / (s0 + 1e-16f);
    float i1 = 1.f / (s1 + 1e-16f);
    float i2 = 1.f / (s2 + 1e-16f);

    // pass 2: weighted accumulation using cached exps
    float acc[6] = {0.f, 0.f, 0.f, 0.f, 0.f, 0.f};
    for (int j = lane; j < cnt; j += 32) {
        int s = g_esrc[start + j];
        float a0, a1, a2;
        if (j < W_CAP) { a0 = ca0[warp][j]; a1 = ca1[warp][j]; a2 = ca2[warp][j]; }
        else {
            float e0 = g_asrc2[s * 3 + 0] + ad0; e0 = e0 >= 0.f ? e0 : NEG_SLOPE * e0;
            float e1 = g_asrc2[s * 3 + 1] + ad1; e1 = e1 >= 0.f ? e1 : NEG_SLOPE * e1;
            float e2 = g_asrc2[s * 3 + 2] + ad2v; e2 = e2 >= 0.f ? e2 : NEG_SLOPE * e2;
            a0 = __expf(e0); a1 = __expf(e1); a2 = __expf(e2);
        }
        const float* hp = g_h2 + (size_t)s * 6;
        acc[0] += hp[0] * a0; acc[1] += hp[1] * a0;
        acc[2] += hp[2] * a1; acc[3] += hp[3] * a1;
        acc[4] += hp[4] * a2; acc[5] += hp[5] * a2;
    }
#pragma unroll
    for (int o = 16; o > 0; o >>= 1)
#pragma unroll
        for (int j = 0; j < 6; j++) acc[j] += __shfl_xor_sync(0xffffffffu, acc[j], o);

    if (lane == 0) {
        out[d * 2 + 0] = (acc[0] * i0 + acc[2] * i1 + acc[4] * i2) * (1.f / 3.f) + bias2[0];
        out[d * 2 + 1] = (acc[1] * i0 + acc[3] * i1 + acc[5] * i2) * (1.f / 3.f) + bias2[1];
    }
}

// ---------------- launch ----------------
extern "C" void kernel_launch(void* const* d_in, const int* in_sizes, int n_in,
                              void* d_out, int out_size) {
    const float* x   = (const float*)d_in[0];
    const void*  ei  = d_in[1];
    const float* W1  = (const float*)d_in[2];
    const float* as1 = (const float*)d_in[3];
    const float* ad1 = (const float*)d_in[4];
    const float* b1  = (const float*)d_in[5];
    const float* W2  = (const float*)d_in[6];
    const float* as2 = (const float*)d_in[7];
    const float* ad2 = (const float*)d_in[8];
    const float* b2  = (const float*)d_in[9];
    float* out = (float*)d_out;

    static cudaStream_t s2 = nullptr;
    static cudaEvent_t evFork = nullptr, evJoin = nullptr;
    if (s2 == nullptr) {
        cudaStreamCreateWithFlags(&s2, cudaStreamNonBlocking);
        cudaEventCreateWithFlags(&evFork, cudaEventDisableTiming);
        cudaEventCreateWithFlags(&evJoin, cudaEventDisableTiming);
    }

    // fork: GEMM chain on s2 (independent of CSR build)
    cudaEventRecord(evFork, 0);
    cudaStreamWaitEvent(s2, evFork, 0);
    convertB_kernel<<<(C_HID * C_IN + 255) / 256, 256, 0, s2>>>(W1);
    gemm1_bf16_kernel<<<(NNODES + 127) / 128, 256, 0, s2>>>(x, as1, ad1);
    cudaEventRecord(evJoin, s2);

    // CSR build on the origin stream (overlaps with GEMM)
    detect_kernel<<<1, 1>>>((const unsigned*)ei);
    init_deg_kernel<<<(NNODES + 255) / 256, 256>>>();
    count_kernel<<<(NEDGES + 255) / 256, 256>>>(ei);
    csr_partial_kernel<<<SCAN_B, 256>>>();
    csr_scanbase_kernel<<<1, 256>>>();
    csr_offsets_kernel<<<SCAN_B, 256>>>();
    scatter_kernel<<<(TOTE + 255) / 256, 256>>>(ei);

    // join: aggregation needs both CSR and GEMM results
    cudaStreamWaitEvent(0, evJoin, 0);
    agg1_kernel<<<(NNODES + 7) / 8, 256>>>(b1, W2, as2, ad2);
    agg2_kernel<<<(NNODES + 7) / 8, 256>>>(b2, out);
}

// round 17
// speedup vs baseline: 3.9121x; 1.3468x over previous
#include <cuda_runtime.h>
#include <cuda_fp16.h>
#include <cstdint>

#define NNODES 50000
#define NEDGES 800000
#define C_IN   512
#define C_HID  128
#define TOTE   (NEDGES + NNODES)   // edges + self loops
#define NEG_SLOPE 0.2f
#define SCAN_B ((NNODES + 255) / 256)   // 196
#define W_CAP 96                        // per-warp exp cache (max degree ~60)

// ---------------- scratch (static __device__, no allocations) ----------------
__device__ __half g_h1h[(size_t)NNODES * C_HID];   // x @ W1, fp16
__device__ float g_asrc1[NNODES];
__device__ float g_adst1[NNODES];
__device__ float g_h2[(size_t)NNODES * 6];
__device__ float g_asrc2[(size_t)NNODES * 3];
__device__ float g_adst2[(size_t)NNODES * 3];
__device__ int   g_deg[NNODES];
__device__ int   g_off[NNODES];
__device__ int   g_pos[NNODES];
__device__ int   g_esrc[TOTE];
__device__ int   g_is64;
__device__ int   g_bsum[SCAN_B];
__device__ int   g_bbase[SCAN_B];
// W1 transposed to col-major fp16 [n][k]
__device__ __align__(16) __half g_Bh[(size_t)C_HID * C_IN];

// ---------------- dtype detection for edge_index ----------------
__global__ void detect_kernel(const unsigned* __restrict__ ei_words) {
    int flag = 1;
    for (int i = 0; i < 64; i++)
        if (ei_words[2 * i + 1] != 0u) { flag = 0; break; }
    g_is64 = flag;
}

__device__ __forceinline__ void load_edge(const void* ei, int e, int& s, int& d) {
    if (g_is64) {
        const long long* p = (const long long*)ei;
        s = (int)p[e];
        d = (int)p[NEDGES + e];
    } else {
        const int* p = (const int*)ei;
        s = p[e];
        d = p[NEDGES + e];
    }
}

// ---------------- CSR build ----------------
__global__ void init_deg_kernel() {
    int i = blockIdx.x * blockDim.x + threadIdx.x;
    if (i < NNODES) g_deg[i] = 1;   // self loop
}

__global__ void count_kernel(const void* __restrict__ ei) {
    int e = blockIdx.x * blockDim.x + threadIdx.x;
    if (e >= NEDGES) return;
    int s, d;
    load_edge(ei, e, s, d);
    atomicAdd(&g_deg[d], 1);
}

__global__ void csr_partial_kernel() {
    int i = blockIdx.x * 256 + threadIdx.x;
    int v = (i < NNODES) ? g_deg[i] : 0;
#pragma unroll
    for (int o = 16; o > 0; o >>= 1) v += __shfl_xor_sync(0xffffffffu, v, o);
    __shared__ int ws[8];
    if ((threadIdx.x & 31) == 0) ws[threadIdx.x >> 5] = v;
    __syncthreads();
    if (threadIdx.x == 0) {
        int s = 0;
#pragma unroll
        for (int w = 0; w < 8; w++) s += ws[w];
        g_bsum[blockIdx.x] = s;
    }
}

__global__ void csr_scanbase_kernel() {
    int t = threadIdx.x;
    int lane = t & 31, w = t >> 5;
    int v = (t < SCAN_B) ? g_bsum[t] : 0;
    int incl = v;
#pragma unroll
    for (int o = 1; o < 32; o <<= 1) {
        int u = __shfl_up_sync(0xffffffffu, incl, o);
        if (lane >= o) incl += u;
    }
    __shared__ int ws[8], ws2[8];
    if (lane == 31) ws[w] = incl;
    __syncthreads();
    if (t < 8) {
        int wv = ws[t];
        int wi = wv;
#pragma unroll
        for (int o = 1; o < 8; o <<= 1) {
            int u = __shfl_up_sync(0xffu, wi, o);
            if (t >= o) wi += u;
        }
        ws2[t] = wi - wv;   // exclusive
    }
    __syncthreads();
    if (t < SCAN_B) g_bbase[t] = ws2[w] + incl - v;
}

__global__ void csr_offsets_kernel() {
    int b = blockIdx.x;
    int t = threadIdx.x;
    int i = b * 256 + t;
    int lane = t & 31, w = t >> 5;
    int v = (i < NNODES) ? g_deg[i] : 0;
    int incl = v;
#pragma unroll
    for (int o = 1; o < 32; o <<= 1) {
        int u = __shfl_up_sync(0xffffffffu, incl, o);
        if (lane >= o) incl += u;
    }
    __shared__ int ws[8], ws2[8];
    if (lane == 31) ws[w] = incl;
    __syncthreads();
    if (t < 8) {
        int wv = ws[t];
        int wi = wv;
#pragma unroll
        for (int o = 1; o < 8; o <<= 1) {
            int u = __shfl_up_sync(0xffu, wi, o);
            if (t >= o) wi += u;
        }
        ws2[t] = wi - wv;
    }
    __syncthreads();
    if (i < NNODES) {
        int off = g_bbase[b] + ws2[w] + incl - v;
        g_off[i] = off;
        g_pos[i] = off;
    }
}

__global__ void scatter_kernel(const void* __restrict__ ei) {
    int idx = blockIdx.x * blockDim.x + threadIdx.x;
    if (idx < NEDGES) {
        int s, d;
        load_edge(ei, idx, s, d);
        int p = atomicAdd(&g_pos[d], 1);
        g_esrc[p] = s;
    } else if (idx < TOTE) {
        int i = idx - NEDGES;           // self loop
        int p = atomicAdd(&g_pos[i], 1);
        g_esrc[p] = i;
    }
}

// ---------------- W1 transpose to fp16 col-major ----------------
__global__ void convertB_kernel(const float* __restrict__ W1) {
    int o = blockIdx.x * 256 + threadIdx.x;     // o = n*512 + k
    if (o >= C_HID * C_IN) return;
    int n = o >> 9, k = o & 511;
    g_Bh[o] = __float2half_rn(W1[(size_t)k * C_HID + n]);
}

// ---------------- tensor-core GEMM: g_h1h = x @ W1 (single-term fp16) -------
// Fused epilogue: fp16 h1 store + fp32 attention dot products.
#define GK 32           // K chunk
#define AS 40           // A smem row stride (halves)
#define BTS 40          // B smem row stride (halves)

__device__ __forceinline__ void mma16816h(float* c, const uint32_t* a,
                                          uint32_t b0, uint32_t b1) {
    asm volatile(
        "mma.sync.aligned.m16n8k16.row.col.f32.f16.f16.f32 "
        "{%0,%1,%2,%3},{%4,%5,%6,%7},{%8,%9},{%0,%1,%2,%3};"
        : "+f"(c[0]), "+f"(c[1]), "+f"(c[2]), "+f"(c[3])
        : "r"(a[0]), "r"(a[1]), "r"(a[2]), "r"(a[3]), "r"(b0), "r"(b1));
}

__global__ __launch_bounds__(256, 2) void gemm1_f16_kernel(
    const float* __restrict__ A,        // x  [NNODES, 512]
    const float* __restrict__ att_src,  // [128]
    const float* __restrict__ att_dst)  // [128]
{
    __shared__ __align__(16) __half Ah[128][AS];
    __shared__ __align__(16) __half Bh_s[128][BTS];
    __shared__ float sAs[128], sAd[128];
    __shared__ float sPs[128][2], sPd[128][2];

    const int tid = threadIdx.x;
    const int lane = tid & 31;
    const int wid = tid >> 5;
    const int warp_m = wid & 3;
    const int warp_n = wid >> 2;
    const int g = lane >> 2;
    const int t4 = lane & 3;
    const int m0 = blockIdx.x * 128;

    if (tid < 128) {
        sAs[tid] = att_src[tid];
        sAd[tid] = att_dst[tid];
    }

    float acc[2][8][4];
#pragma unroll
    for (int mi = 0; mi < 2; mi++)
#pragma unroll
        for (int ni = 0; ni < 8; ni++)
#pragma unroll
            for (int q = 0; q < 4; q++) acc[mi][ni][q] = 0.f;

    float4 pa[4];
    uint4 pbh[2];

#pragma unroll
    for (int i = 0; i < 4; i++) {
        int flat = i * 256 + tid;
        int row = flat >> 3, c4 = (flat & 7) * 4;
        int gr = m0 + row;
        pa[i] = (gr < NNODES) ? *(const float4*)(A + (size_t)gr * C_IN + c4)
                              : make_float4(0.f, 0.f, 0.f, 0.f);
    }
#pragma unroll
    for (int i = 0; i < 2; i++) {
        int u = i * 256 + tid;
        int n = u >> 2, kq = u & 3;
        pbh[i] = *(const uint4*)(g_Bh + (size_t)n * C_IN + kq * 8);
    }

    for (int kc = 0; kc < C_IN / GK; kc++) {
#pragma unroll
        for (int i = 0; i < 4; i++) {
            int flat = i * 256 + tid;
            int row = flat >> 3, c4 = (flat & 7) * 4;
            float4 v = pa[i];
            *(__half2*)&Ah[row][c4]     = __floats2half2_rn(v.x, v.y);
            *(__half2*)&Ah[row][c4 + 2] = __floats2half2_rn(v.z, v.w);
        }
#pragma unroll
        for (int i = 0; i < 2; i++) {
            int u = i * 256 + tid;
            int n = u >> 2, kq = u & 3;
            *(uint4*)&Bh_s[n][kq * 8] = pbh[i];
        }
        __syncthreads();

        if (kc + 1 < C_IN / GK) {
            int k0n = (kc + 1) * GK;
#pragma unroll
            for (int i = 0; i < 4; i++) {
                int flat = i * 256 + tid;
                int row = flat >> 3, c4 = (flat & 7) * 4;
                int gr = m0 + row;
                pa[i] = (gr < NNODES)
                          ? *(const float4*)(A + (size_t)gr * C_IN + k0n + c4)
                          : make_float4(0.f, 0.f, 0.f, 0.f);
            }
#pragma unroll
            for (int i = 0; i < 2; i++) {
                int u = i * 256 + tid;
                int n = u >> 2, kq = u & 3;
                pbh[i] = *(const uint4*)(g_Bh + (size_t)n * C_IN + k0n + kq * 8);
            }
        }

#pragma unroll
        for (int s = 0; s < GK; s += 16) {
            uint32_t ah[2][4];
#pragma unroll
            for (int mi = 0; mi < 2; mi++) {
                int r = warp_m * 32 + mi * 16 + g;
                int c = s + t4 * 2;
                ah[mi][0] = *(const uint32_t*)&Ah[r][c];
                ah[mi][1] = *(const uint32_t*)&Ah[r + 8][c];
                ah[mi][2] = *(const uint32_t*)&Ah[r][c + 8];
                ah[mi][3] = *(const uint32_t*)&Ah[r + 8][c + 8];
            }
            int k0 = s + t4 * 2;
#pragma unroll
            for (int ni = 0; ni < 8; ni++) {
                int n = warp_n * 64 + ni * 8 + g;
                uint32_t bh0 = *(const uint32_t*)&Bh_s[n][k0];
                uint32_t bh1 = *(const uint32_t*)&Bh_s[n][k0 + 8];
#pragma unroll
                for (int mi = 0; mi < 2; mi++)
                    mma16816h(acc[mi][ni], ah[mi], bh0, bh1);
            }
        }
        __syncthreads();
    }

    // ---- epilogue: store fp16 h1 + fused fp32 attention dot products ----
#pragma unroll
    for (int mi = 0; mi < 2; mi++) {
        float psA = 0.f, psB = 0.f, pdA = 0.f, pdB = 0.f;
#pragma unroll
        for (int ni = 0; ni < 8; ni++) {
            int r = m0 + warp_m * 32 + mi * 16 + g;
            int c = warp_n * 64 + ni * 8 + t4 * 2;
            if (r < NNODES)
                *(__half2*)(g_h1h + (size_t)r * C_HID + c) =
                    __floats2half2_rn(acc[mi][ni][0], acc[mi][ni][1]);
            if (r + 8 < NNODES)
                *(__half2*)(g_h1h + (size_t)(r + 8) * C_HID + c) =
                    __floats2half2_rn(acc[mi][ni][2], acc[mi][ni][3]);
            float a0 = sAs[c], a1 = sAs[c + 1];
            float d0 = sAd[c], d1 = sAd[c + 1];
            psA += acc[mi][ni][0] * a0 + acc[mi][ni][1] * a1;
            psB += acc[mi][ni][2] * a0 + acc[mi][ni][3] * a1;
            pdA += acc[mi][ni][0] * d0 + acc[mi][ni][1] * d1;
            pdB += acc[mi][ni][2] * d0 + acc[mi][ni][3] * d1;
        }
#pragma unroll
        for (int o = 1; o <= 2; o <<= 1) {
            psA += __shfl_xor_sync(0xffffffffu, psA, o);
            psB += __shfl_xor_sync(0xffffffffu, psB, o);
            pdA += __shfl_xor_sync(0xffffffffu, pdA, o);
            pdB += __shfl_xor_sync(0xffffffffu, pdB, o);
        }
        if (t4 == 0) {
            int rl = warp_m * 32 + mi * 16 + g;
            sPs[rl][warp_n] = psA;  sPs[rl + 8][warp_n] = psB;
            sPd[rl][warp_n] = pdA;  sPd[rl + 8][warp_n] = pdB;
        }
    }
    __syncthreads();
    if (tid < 128) {
        int r = m0 + tid;
        if (r < NNODES) {
            g_asrc1[r] = sPs[tid][0] + sPs[tid][1];
            g_adst1[r] = sPd[tid][0] + sPd[tid][1];
        }
    }
}

// ---------------- layer-1 aggregation + FUSED layer-2 projection -----------
__global__ __launch_bounds__(256) void agg1_kernel(const float* __restrict__ bias1,
                                                   const float* __restrict__ W2,
                                                   const float* __restrict__ as2,
                                                   const float* __restrict__ ad2) {
    __shared__ float exw[8][W_CAP];
    __shared__ float sW2[C_HID * 6];
    __shared__ float sa2[6], sd2[6];

    int tid = threadIdx.x;
    for (int i = tid; i < C_HID * 6; i += 256) sW2[i] = W2[i];
    if (tid < 6) { sa2[tid] = as2[tid]; sd2[tid] = ad2[tid]; }
    __syncthreads();

    int warp = tid >> 5;
    int lane = tid & 31;
    int d = blockIdx.x * 8 + warp;
    if (d >= NNODES) return;

    int start = g_off[d];
    int cnt = g_deg[d];
    float adst = g_adst1[d];

    float sum = 0.f;
    for (int j = lane; j < cnt; j += 32) {
        int s = g_esrc[start + j];
        float e = g_asrc1[s] + adst;
        e = e >= 0.f ? e : NEG_SLOPE * e;
        float ex = __expf(e);
        if (j < W_CAP) exw[warp][j] = ex;
        sum += ex;
    }
    __syncwarp();
#pragma unroll
    for (int o = 16; o > 0; o >>= 1) sum += __shfl_xor_sync(0xffffffffu, sum, o);
    float inv = 1.f / (sum + 1e-16f);

    float4 acc = make_float4(0.f, 0.f, 0.f, 0.f);
    float4 accB = make_float4(0.f, 0.f, 0.f, 0.f);
    int j = 0;
    for (; j + 1 < cnt; j += 2) {
        int s0 = g_esrc[start + j];
        int s1 = g_esrc[start + j + 1];
        float ex0, ex1;
        if (j < W_CAP) ex0 = exw[warp][j];
        else {
            float e = g_asrc1[s0] + adst;
            e = e >= 0.f ? e : NEG_SLOPE * e;
            ex0 = __expf(e);
        }
        if (j + 1 < W_CAP) ex1 = exw[warp][j + 1];
        else {
            float e = g_asrc1[s1] + adst;
            e = e >= 0.f ? e : NEG_SLOPE * e;
            ex1 = __expf(e);
        }
        uint2 r0 = *(const uint2*)(g_h1h + (size_t)s0 * C_HID + lane * 4);
        uint2 r1 = *(const uint2*)(g_h1h + (size_t)s1 * C_HID + lane * 4);
        float2 a01 = __half22float2(*(const __half2*)&r0.x);
        float2 a23 = __half22float2(*(const __half2*)&r0.y);
        float2 b01 = __half22float2(*(const __half2*)&r1.x);
        float2 b23 = __half22float2(*(const __half2*)&r1.y);
        acc.x += a01.x * ex0;  acc.y += a01.y * ex0;
        acc.z += a23.x * ex0;  acc.w += a23.y * ex0;
        accB.x += b01.x * ex1; accB.y += b01.y * ex1;
        accB.z += b23.x * ex1; accB.w += b23.y * ex1;
    }
    if (j < cnt) {
        int s0 = g_esrc[start + j];
        float ex0;
        if (j < W_CAP) ex0 = exw[warp][j];
        else {
            float e = g_asrc1[s0] + adst;
            e = e >= 0.f ? e : NEG_SLOPE * e;
            ex0 = __expf(e);
        }
        uint2 r0 = *(const uint2*)(g_h1h + (size_t)s0 * C_HID + lane * 4);
        float2 a01 = __half22float2(*(const __half2*)&r0.x);
        float2 a23 = __half22float2(*(const __half2*)&r0.y);
        acc.x += a01.x * ex0; acc.y += a01.y * ex0;
        acc.z += a23.x * ex0; acc.w += a23.y * ex0;
    }
    acc.x += accB.x; acc.y += accB.y; acc.z += accB.z; acc.w += accB.w;

    float4 b4 = *(const float4*)(bias1 + lane * 4);
    float vx = acc.x * inv + b4.x; vx = vx > 0.f ? vx : 0.f;
    float vy = acc.y * inv + b4.y; vy = vy > 0.f ? vy : 0.f;
    float vz = acc.z * inv + b4.z; vz = vz > 0.f ? vz : 0.f;
    float vw = acc.w * inv + b4.w; vw = vw > 0.f ? vw : 0.f;

    float p[6];
    {
        int c = lane * 4;
        const float* w0 = &sW2[(c + 0) * 6];
        const float* w1 = &sW2[(c + 1) * 6];
        const float* w2r = &sW2[(c + 2) * 6];
        const float* w3 = &sW2[(c + 3) * 6];
#pragma unroll
        for (int jj = 0; jj < 6; jj++)
            p[jj] = vx * w0[jj] + vy * w1[jj] + vz * w2r[jj] + vw * w3[jj];
    }
#pragma unroll
    for (int o = 16; o > 0; o >>= 1)
#pragma unroll
        for (int jj = 0; jj < 6; jj++) p[jj] += __shfl_xor_sync(0xffffffffu, p[jj], o);

    if (lane == 0) {
        float* hp = g_h2 + (size_t)d * 6;
#pragma unroll
        for (int jj = 0; jj < 6; jj++) hp[jj] = p[jj];
        g_asrc2[d * 3 + 0] = p[0] * sa2[0] + p[1] * sa2[1];
        g_asrc2[d * 3 + 1] = p[2] * sa2[2] + p[3] * sa2[3];
        g_asrc2[d * 3 + 2] = p[4] * sa2[4] + p[5] * sa2[5];
        g_adst2[d * 3 + 0] = p[0] * sd2[0] + p[1] * sd2[1];
        g_adst2[d * 3 + 1] = p[2] * sd2[2] + p[3] * sd2[3];
        g_adst2[d * 3 + 2] = p[4] * sd2[4] + p[5] * sd2[5];
    }
}

// ---------------- layer-2 aggregation + head mean (warp per dst node) ------
__global__ __launch_bounds__(256) void agg2_kernel(const float* __restrict__ bias2,
                                                   float* __restrict__ out) {
    __shared__ float ca0[8][W_CAP], ca1[8][W_CAP], ca2[8][W_CAP];
    int warp = threadIdx.x >> 5;
    int lane = threadIdx.x & 31;
    int d = blockIdx.x * 8 + warp;
    if (d >= NNODES) return;

    int start = g_off[d];
    int cnt = g_deg[d];

    float ad0 = g_adst2[d * 3 + 0];
    float ad1 = g_adst2[d * 3 + 1];
    float ad2v = g_adst2[d * 3 + 2];

    float s0 = 0.f, s1 = 0.f, s2 = 0.f;
    for (int j = lane; j < cnt; j += 32) {
        int s = g_esrc[start + j];
        float e0 = g_asrc2[s * 3 + 0] + ad0; e0 = e0 >= 0.f ? e0 : NEG_SLOPE * e0;
        float e1 = g_asrc2[s * 3 + 1] + ad1; e1 = e1 >= 0.f ? e1 : NEG_SLOPE * e1;
        float e2 = g_asrc2[s * 3 + 2] + ad2v; e2 = e2 >= 0.f ? e2 : NEG_SLOPE * e2;
        float a0 = __expf(e0), a1 = __expf(e1), a2 = __expf(e2);
        if (j < W_CAP) { ca0[warp][j] = a0; ca1[warp][j] = a1; ca2[warp][j] = a2; }
        s0 += a0; s1 += a1; s2 += a2;
    }
    __syncwarp();
#pragma unroll
    for (int o = 16; o > 0; o >>= 1) {
        s0 += __shfl_xor_sync(0xffffffffu, s0, o);
        s1 += __shfl_xor_sync(0xffffffffu, s1, o);
        s2 += __shfl_xor_sync(0xffffffffu, s2, o);
    }
    float i0 = 1.f / (s0 + 1e-16f);
    float i1 = 1.f / (s1 + 1e-16f);
    float i2 = 1.f / (s2 + 1e-16f);

    float acc[6] = {0.f, 0.f, 0.f, 0.f, 0.f, 0.f};
    for (int j = lane; j < cnt; j += 32) {
        int s = g_esrc[start + j];
        float a0, a1, a2;
        if (j < W_CAP) { a0 = ca0[warp][j]; a1 = ca1[warp][j]; a2 = ca2[warp][j]; }
        else {
            float e0 = g_asrc2[s * 3 + 0] + ad0; e0 = e0 >= 0.f ? e0 : NEG_SLOPE * e0;
            float e1 = g_asrc2[s * 3 + 1] + ad1; e1 = e1 >= 0.f ? e1 : NEG_SLOPE * e1;
            float e2 = g_asrc2[s * 3 + 2] + ad2v; e2 = e2 >= 0.f ? e2 : NEG_SLOPE * e2;
            a0 = __expf(e0); a1 = __expf(e1); a2 = __expf(e2);
        }
        const float* hp = g_h2 + (size_t)s * 6;
        acc[0] += hp[0] * a0; acc[1] += hp[1] * a0;
        acc[2] += hp[2] * a1; acc[3] += hp[3] * a1;
        acc[4] += hp[4] * a2; acc[5] += hp[5] * a2;
    }
#pragma unroll
    for (int o = 16; o > 0; o >>= 1)
#pragma unroll
        for (int j = 0; j < 6; j++) acc[j] += __shfl_xor_sync(0xffffffffu, acc[j], o);

    if (lane == 0) {
        out[d * 2 + 0] = (acc[0] * i0 + acc[2] * i1 + acc[4] * i2) * (1.f / 3.f) + bias2[0];
        out[d * 2 + 1] = (acc[1] * i0 + acc[3] * i1 + acc[5] * i2) * (1.f / 3.f) + bias2[1];
    }
}

// ---------------- launch ----------------
extern "C" void kernel_launch(void* const* d_in, const int* in_sizes, int n_in,
                              void* d_out, int out_size) {
    const float* x   = (const float*)d_in[0];
    const void*  ei  = d_in[1];
    const float* W1  = (const float*)d_in[2];
    const float* as1 = (const float*)d_in[3];
    const float* ad1 = (const float*)d_in[4];
    const float* b1  = (const float*)d_in[5];
    const float* W2  = (const float*)d_in[6];
    const float* as2 = (const float*)d_in[7];
    const float* ad2 = (const float*)d_in[8];
    const float* b2  = (const float*)d_in[9];
    float* out = (float*)d_out;

    static cudaStream_t s2 = nullptr;
    static cudaEvent_t evFork = nullptr, evJoin = nullptr;
    if (s2 == nullptr) {
        cudaStreamCreateWithFlags(&s2, cudaStreamNonBlocking);
        cudaEventCreateWithFlags(&evFork, cudaEventDisableTiming);
        cudaEventCreateWithFlags(&evJoin, cudaEventDisableTiming);
    }

    // fork: GEMM chain on s2 (independent of CSR build)
    cudaEventRecord(evFork, 0);
    cudaStreamWaitEvent(s2, evFork, 0);
    convertB_kernel<<<(C_HID * C_IN + 255) / 256, 256, 0, s2>>>(W1);
    gemm1_f16_kernel<<<(NNODES + 127) / 128, 256, 0, s2>>>(x, as1, ad1);
    cudaEventRecord(evJoin, s2);

    // CSR build on the origin stream (overlaps with GEMM)
    detect_kernel<<<1, 1>>>((const unsigned*)ei);
    init_deg_kernel<<<(NNODES + 255) / 256, 256>>>();
    count_kernel<<<(NEDGES + 255) / 256, 256>>>(ei);
    csr_partial_kernel<<<SCAN_B, 256>>>();
    csr_scanbase_kernel<<<1, 256>>>();
    csr_offsets_kernel<<<SCAN_B, 256>>>();
    scatter_kernel<<<(TOTE + 255) / 256, 256>>>(ei);

    // join: aggregation needs both CSR and GEMM results
    cudaStreamWaitEvent(0, evJoin, 0);
    agg1_kernel<<<(NNODES + 7) / 8, 256>>>(b1, W2, as2, ad2);
    agg2_kernel<<<(NNODES + 7) / 8, 256>>>(b2, out);
}